// round 14
// baseline (speedup 1.0000x reference)
#include <cuda_runtime.h>
#include <cuda_bf16.h>
#include <math.h>
#include <stdint.h>

typedef unsigned long long u64;

#define NT   4096   // B*T
#define CC   128    // n_embed
#define TT   32     // block_size
#define NH   4      // heads
#define HS   32     // head size
#define NE   4      // experts
#define NL   4      // layers
#define VV   50257  // vocab
#define FF   512    // 4*C

#define LM_NPAD 50688                 // >= VV, multiple of 256
#define LMS     136                   // padded k-stride (272B = 17*16B)
#define LM_SMEM (2*128*LMS*2 + 2*64*LMS*2)   // 104448 bytes
#define LM_NTILES 4                   // n-tiles per CTA (A reuse)

// -------------------- scratch (device globals; no allocs allowed) ---------
__device__ float g_x   [NT*CC];
__device__ float g_h   [NT*CC];
__device__ float g_qkv [NT*3*CC];
__device__ float g_att [NT*CC];
__device__ float g_nx  [NT*CC];
__device__ float g_h1c [(size_t)NE*NT*FF];
__device__ float g_eoc [(size_t)NE*NT*CC];
__device__ float g_gates[NT*NE];
__device__ int   g_cnt [NE];
__device__ int   g_list[NE*NT];
__device__ int4  g_slot[NT];
__device__ float g_wpack[(size_t)NL*CC*3*CC];
__device__ __nv_bfloat16 g_bh[(size_t)LM_NPAD*CC];   // Wlm^T hi  [n][k]
__device__ __nv_bfloat16 g_bl[(size_t)LM_NPAD*CC];   // Wlm^T lo
__device__ __nv_bfloat16 g_ah[(size_t)NT*CC];        // h hi
__device__ __nv_bfloat16 g_al[(size_t)NT*CC];        // h lo

// -------------------- baseline-PTX mma helpers -----------------------------
__device__ __forceinline__ uint32_t smem_u32(const void* p){
    uint32_t a;
    asm("{ .reg .u64 t; cvta.to.shared.u64 t, %1; cvt.u32.u64 %0, t; }" : "=r"(a) : "l"(p));
    return a;
}
__device__ __forceinline__ void ldmatrix_x4(uint32_t* r, uint32_t addr){
    asm volatile("ldmatrix.sync.aligned.m8n8.x4.shared.b16 {%0,%1,%2,%3}, [%4];"
                 : "=r"(r[0]),"=r"(r[1]),"=r"(r[2]),"=r"(r[3]) : "r"(addr));
}
__device__ __forceinline__ void ldmatrix_x2(uint32_t* r, uint32_t addr){
    asm volatile("ldmatrix.sync.aligned.m8n8.x2.shared.b16 {%0,%1}, [%2];"
                 : "=r"(r[0]),"=r"(r[1]) : "r"(addr));
}
__device__ __forceinline__ void mma16816(float* c, const uint32_t* a, const uint32_t* b){
    asm volatile("mma.sync.aligned.m16n8k16.row.col.f32.bf16.bf16.f32 "
        "{%0,%1,%2,%3}, {%4,%5,%6,%7}, {%8,%9}, {%0,%1,%2,%3};"
        : "+f"(c[0]),"+f"(c[1]),"+f"(c[2]),"+f"(c[3])
        : "r"(a[0]),"r"(a[1]),"r"(a[2]),"r"(a[3]), "r"(b[0]),"r"(b[1]));
}

// -------------------- threefry2x32 (JAX-compatible) -----------------------
__device__ __forceinline__ unsigned rotl32(unsigned v, int r){ return (v<<r)|(v>>(32-r)); }

__device__ void threefry2x32(unsigned k0, unsigned k1, unsigned x0, unsigned x1,
                             unsigned &o0, unsigned &o1)
{
    unsigned ks0=k0, ks1=k1, ks2 = k0 ^ k1 ^ 0x1BD11BDAu;
    x0 += ks0; x1 += ks1;
#define TF_RND(r) { x0 += x1; x1 = rotl32(x1, r); x1 ^= x0; }
    TF_RND(13) TF_RND(15) TF_RND(26) TF_RND(6)
    x0 += ks1; x1 += ks2 + 1u;
    TF_RND(17) TF_RND(29) TF_RND(16) TF_RND(24)
    x0 += ks2; x1 += ks0 + 2u;
    TF_RND(13) TF_RND(15) TF_RND(26) TF_RND(6)
    x0 += ks0; x1 += ks1 + 3u;
    TF_RND(17) TF_RND(29) TF_RND(16) TF_RND(24)
    x0 += ks1; x1 += ks2 + 4u;
    TF_RND(13) TF_RND(15) TF_RND(26) TF_RND(6)
    x0 += ks2; x1 += ks0 + 5u;
#undef TF_RND
    o0 = x0; o1 = x1;
}

__device__ float erfinv_f(float x)
{
    float w = -log1pf(-x*x);
    float p;
    if (w < 5.0f) {
        w = w - 2.5f;
        p =               2.81022636e-08f;
        p = fmaf(p, w,    3.43273939e-07f);
        p = fmaf(p, w,   -3.5233877e-06f);
        p = fmaf(p, w,   -4.39150654e-06f);
        p = fmaf(p, w,    0.00021858087f);
        p = fmaf(p, w,   -0.00125372503f);
        p = fmaf(p, w,   -0.00417768164f);
        p = fmaf(p, w,    0.246640727f);
        p = fmaf(p, w,    1.50140941f);
    } else {
        w = sqrtf(w) - 3.0f;
        p =              -0.000200214257f;
        p = fmaf(p, w,    0.000100950558f);
        p = fmaf(p, w,    0.00134934322f);
        p = fmaf(p, w,   -0.00367342844f);
        p = fmaf(p, w,    0.00573950773f);
        p = fmaf(p, w,   -0.0076224613f);
        p = fmaf(p, w,    0.00943887047f);
        p = fmaf(p, w,    1.00167406f);
        p = fmaf(p, w,    2.83297682f);
    }
    return p * x;
}

__device__ float jax_normal_elem(unsigned i)
{
    unsigned y0, y1;
    threefry2x32(0u, 42u, 0u, i, y0, y1);
    unsigned bits = y0 ^ y1;
    float f  = __uint_as_float((bits >> 9) | 0x3f800000u) - 1.0f;
    const float lo = -0.99999994f;
    float u = fmaxf(lo, fmaf(f, 2.0f, lo));
    return 1.41421356f * erfinv_f(u);
}

// -------------------- small kernels ---------------------------------------
__global__ void embed_k(const int* __restrict__ idx, const float* __restrict__ tok,
                        const float* __restrict__ pos, float* __restrict__ x)
{
    int gid = blockIdx.x * blockDim.x + threadIdx.x;
    int r = gid >> 7, c = gid & 127;
    int t = r & (TT - 1);
    x[gid] = tok[idx[r] * CC + c] + pos[t * CC + c];
}

__global__ void layernorm_k(const float* __restrict__ x, const float* __restrict__ g,
                            const float* __restrict__ b, float* __restrict__ out)
{
    int row = blockIdx.x, c = threadIdx.x;
    __shared__ float red[CC];
    float v = x[row * CC + c];
    red[c] = v; __syncthreads();
    for (int s = 64; s > 0; s >>= 1) { if (c < s) red[c] += red[c + s]; __syncthreads(); }
    float mean = red[0] * (1.0f / CC);
    __syncthreads();
    float d = v - mean;
    red[c] = d * d; __syncthreads();
    for (int s = 64; s > 0; s >>= 1) { if (c < s) red[c] += red[c + s]; __syncthreads(); }
    float var = red[0] * (1.0f / CC);
    out[row * CC + c] = d / sqrtf(var + 1e-5f) * g[c] + b[c];
}

__global__ void pack_qkv_all_k(const float* __restrict__ Wq, const float* __restrict__ Wk,
                               const float* __restrict__ Wv, float* __restrict__ wp)
{
    int gid = blockIdx.x * blockDim.x + threadIdx.x;   // NL*CC*384
    int l   = gid / (CC * 384);
    int rem = gid % (CC * 384);
    int c = rem / 384, j = rem % 384;
    size_t lw = (size_t)l * NH * CC * HS;
    const float* W = (j < 128) ? (Wq + lw) : (j < 256 ? (Wk + lw) : (Wv + lw));
    int jj = j & 127;
    int hh = jj >> 5, dd = jj & 31;
    wp[gid] = W[(hh * CC + c) * HS + dd];
}

// pack Wlm -> transposed bf16 hi/lo: bpack[n][k] = bf16split(Wlm[k][n])
__global__ void pack_b_k(const float* __restrict__ Wlm,
                         __nv_bfloat16* __restrict__ bh, __nv_bfloat16* __restrict__ bl)
{
    __shared__ float s[32][33];
    int n0 = blockIdx.x * 32, k0 = blockIdx.y * 32;
    int tx = threadIdx.x, ty = threadIdx.y;
    int n = n0 + tx;
    s[ty][tx] = (n < VV) ? Wlm[(size_t)(k0 + ty) * VV + n] : 0.f;
    __syncthreads();
    float f = s[tx][ty];
    __nv_bfloat16 hi = __float2bfloat16(f);
    float lo = f - __bfloat162float(hi);
    size_t o = (size_t)(n0 + ty) * CC + k0 + tx;
    bh[o] = hi;
    bl[o] = __float2bfloat16(lo);
}

__global__ void pack_a_k(const float* __restrict__ h,
                         __nv_bfloat16* __restrict__ ah, __nv_bfloat16* __restrict__ al)
{
    int i = blockIdx.x * blockDim.x + threadIdx.x;
    float f = h[i];
    __nv_bfloat16 hi = __float2bfloat16(f);
    ah[i] = hi;
    al[i] = __float2bfloat16(f - __bfloat162float(hi));
}

__global__ void attention_k(const float* __restrict__ qkv, float* __restrict__ att)
{
    int b = blockIdx.x >> 2, h = blockIdx.x & 3;
    int t = threadIdx.y, s = threadIdx.x;
    __shared__ float qs[TT][HS+1], ks[TT][HS+1], vs[TT][HS+1], ws[TT][TT+1];
    int base = (b * TT + t) * (3 * CC) + h * HS;
    qs[t][s] = qkv[base + s];
    ks[t][s] = qkv[base + CC + s];
    vs[t][s] = qkv[base + 2 * CC + s];
    __syncthreads();
    const float NEG_INF = __int_as_float(0xff800000);
    float w;
    if (s <= t) {
        float acc = 0.f;
#pragma unroll
        for (int d = 0; d < HS; d++) acc = fmaf(qs[t][d], ks[s][d], acc);
        w = acc * 0.08838834764831845f;
    } else w = NEG_INF;
    float m = w;
#pragma unroll
    for (int o = 16; o; o >>= 1) m = fmaxf(m, __shfl_xor_sync(0xffffffffu, m, o));
    float e = (s <= t) ? expf(w - m) : 0.f;
    float sum = e;
#pragma unroll
    for (int o = 16; o; o >>= 1) sum += __shfl_xor_sync(0xffffffffu, sum, o);
    ws[t][s] = e / sum;
    __syncthreads();
    float acc = 0.f;
#pragma unroll
    for (int k = 0; k < TT; k++) acc = fmaf(ws[t][k], vs[k][s], acc);
    att[(b * TT + t) * CC + h * HS + s] = acc;
}

__global__ void reset_cnt_k(int* __restrict__ cnt)
{
    if (threadIdx.x < NE) cnt[threadIdx.x] = 0;
}

__global__ void router_ln_k(const float* __restrict__ x,
                            const float* __restrict__ g2, const float* __restrict__ b2,
                            const float* __restrict__ Wr, const float* __restrict__ br,
                            const float* __restrict__ Wn, const float* __restrict__ bn,
                            const float* __restrict__ Ws, const float* __restrict__ bs,
                            float* __restrict__ nx, float* __restrict__ gates,
                            int* __restrict__ cnt, int* __restrict__ list,
                            int4* __restrict__ slot, int layer)
{
    int row = blockIdx.x, c = threadIdx.x;
    __shared__ float red[9][CC];
    float xv = x[row * CC + c];
    red[0][c] = xv; __syncthreads();
    for (int s = 64; s > 0; s >>= 1) { if (c < s) red[0][c] += red[0][c + s]; __syncthreads(); }
    float mean = red[0][0] * (1.0f / CC);
    __syncthreads();
    float d = xv - mean;
    red[0][c] = d * d; __syncthreads();
    for (int s = 64; s > 0; s >>= 1) { if (c < s) red[0][c] += red[0][c + s]; __syncthreads(); }
    float var = red[0][0] * (1.0f / CC);
    __syncthreads();
    float v = d / sqrtf(var + 1e-5f) * g2[c] + b2[c];
    nx[row * CC + c] = v;
#pragma unroll
    for (int e = 0; e < NE; e++) {
        red[e][c]     = v * Wr[c * NE + e];
        red[4 + e][c] = v * Wn[c * NE + e];
    }
    red[8][c] = v * Ws[c];
    __syncthreads();
    for (int st = 64; st > 0; st >>= 1) {
        if (c < st) {
#pragma unroll
            for (int j = 0; j < 9; j++) red[j][c] += red[j][c + st];
        }
        __syncthreads();
    }
    if (c == 0) {
        float noisy[NE];
#pragma unroll
        for (int e = 0; e < NE; e++) {
            float logit = red[e][0] + br[e];
            float nl    = red[4 + e][0] + bn[e];
            float sp    = fmaxf(nl, 0.f) + log1pf(expf(-fabsf(nl)));
            unsigned i  = ((unsigned)(layer * NT + row)) * NE + e;
            noisy[e]    = logit + jax_normal_elem(i) * sp;
        }
        int i1 = 0;
        for (int e = 1; e < NE; e++) if (noisy[e] > noisy[i1]) i1 = e;
        int i2 = -1;
        for (int e = 0; e < NE; e++) if (e != i1 && (i2 < 0 || noisy[e] > noisy[i2])) i2 = e;
        float mx = noisy[i1];
        float gv[NE], gsum = 0.f;
#pragma unroll
        for (int e = 0; e < NE; e++) {
            gv[e] = (e == i1 || e == i2) ? expf(noisy[e] - mx) : 0.f;
            gsum += gv[e];
        }
#pragma unroll
        for (int e = 0; e < NE; e++) gates[row * NE + e] = gv[e] / gsum;
        int skipped = (red[8][0] + bs[0] > 0.f);
        if (!skipped) {
            int ea = i1 < i2 ? i1 : i2;
            int eb = i1 < i2 ? i2 : i1;
            int pa = atomicAdd(&cnt[ea], 1); list[ea * NT + pa] = row;
            int pb = atomicAdd(&cnt[eb], 1); list[eb * NT + pb] = row;
            slot[row] = make_int4(ea, pa, eb, pb);
        } else {
            slot[row] = make_int4(-1, 0, -1, 0);
        }
    }
}

// fused combine + next layernorm; also zeroes cnt for the NEXT layer's router
__global__ void combine_ln_k(float* __restrict__ x, const float* __restrict__ eoc,
                             const int4* __restrict__ slot,
                             const float* __restrict__ g, const float* __restrict__ b,
                             float* __restrict__ hout, int* __restrict__ cnt)
{
    int row = blockIdx.x, c = threadIdx.x;
    __shared__ float red[CC];
    int4 s = slot[row];
    float v = x[row * CC + c];
    if (s.x >= 0)
        v += eoc[((size_t)s.x * NT + s.y) * CC + c]
           + eoc[((size_t)s.z * NT + s.w) * CC + c];
    x[row * CC + c] = v;
    if (row == 0 && c < NE) cnt[c] = 0;      // reset for next layer's router
    red[c] = v; __syncthreads();
    for (int st = 64; st > 0; st >>= 1) { if (c < st) red[c] += red[c + st]; __syncthreads(); }
    float mean = red[0] * (1.0f / CC);
    __syncthreads();
    float d = v - mean;
    red[c] = d * d; __syncthreads();
    for (int st = 64; st > 0; st >>= 1) { if (c < st) red[c] += red[c + st]; __syncthreads(); }
    float var = red[0] * (1.0f / CC);
    hout[row * CC + c] = d / sqrtf(var + 1e-5f) * g[c] + b[c];
}

// -------------------- FFMA2 helper ----------------------------------------
__device__ __forceinline__ void ffma2(u64 &d, u64 a, u64 b)
{
    asm("fma.rn.f32x2 %0, %1, %2, %0;" : "+l"(d) : "l"(a), "l"(b));
}

enum { EPI_BIAS = 0, EPI_RELU = 1, EPI_RESID = 2, EPI_GATE_WR = 3 };

// -------------------- 64x64 SGEMM (proj only) ------------------------------
#define BM 64
#define BN 64
#define BK 16

template<int EPI>
__global__ void __launch_bounds__(256, 4)
sgemm_k(const float* __restrict__ A, const float* __restrict__ B,
        const float* __restrict__ bias, float* __restrict__ C,
        int M, int N, int K)
{
    __shared__ float2 As2[BK][BM];
    __shared__ float  Bs [BK][BN];
    int tid = threadIdx.x;
    int n0 = blockIdx.x * BN, m0 = blockIdx.y * BM;
    int tx = tid & 15, ty = tid >> 4;
    int am = tid >> 2,  ak = (tid & 3) * 4;
    int bk = tid >> 4,  bn = (tid & 15) * 4;

    u64 acc[4][2];
#pragma unroll
    for (int i = 0; i < 4; i++) { acc[i][0] = 0ull; acc[i][1] = 0ull; }

    for (int k0 = 0; k0 < K; k0 += BK) {
        float4 av = *reinterpret_cast<const float4*>(&A[(size_t)(m0 + am) * K + k0 + ak]);
        As2[ak + 0][am] = make_float2(av.x, av.x);
        As2[ak + 1][am] = make_float2(av.y, av.y);
        As2[ak + 2][am] = make_float2(av.z, av.z);
        As2[ak + 3][am] = make_float2(av.w, av.w);
        const float* Brow = &B[(size_t)(k0 + bk) * N + n0 + bn];
        Bs[bk][bn + 0] = Brow[0]; Bs[bk][bn + 1] = Brow[1];
        Bs[bk][bn + 2] = Brow[2]; Bs[bk][bn + 3] = Brow[3];
        __syncthreads();
#pragma unroll
        for (int k = 0; k < BK; k++) {
            u64 a[4];
#pragma unroll
            for (int i = 0; i < 4; i++)
                a[i] = *reinterpret_cast<const u64*>(&As2[k][ty * 4 + i]);
            ulonglong2 bv = *reinterpret_cast<const ulonglong2*>(&Bs[k][tx * 4]);
#pragma unroll
            for (int i = 0; i < 4; i++) {
                ffma2(acc[i][0], a[i], bv.x);
                ffma2(acc[i][1], a[i], bv.y);
            }
        }
        __syncthreads();
    }

#pragma unroll
    for (int i = 0; i < 4; i++) {
        int m = m0 + ty * 4 + i;
#pragma unroll
        for (int p = 0; p < 2; p++) {
            float vlo = __uint_as_float((unsigned)(acc[i][p] & 0xffffffffull));
            float vhi = __uint_as_float((unsigned)(acc[i][p] >> 32));
#pragma unroll
            for (int q = 0; q < 2; q++) {
                int n = n0 + tx * 4 + p * 2 + q;
                float val = (q == 0 ? vlo : vhi) + (bias ? bias[n] : 0.f);
                size_t o = (size_t)m * N + n;
                if      (EPI == EPI_BIAS)  C[o] = val;
                else if (EPI == EPI_RESID) C[o] = C[o] + val;
            }
        }
    }
}

// -------------------- 128x128 SGEMM (QKV / MoE compact) --------------------
#define QM 128
#define QN 128
#define QK 16

template<int EPI, int INDA>
__global__ void __launch_bounds__(256, 2)
sgemm128_k(const float* __restrict__ A, const float* __restrict__ B,
           const float* __restrict__ bias, float* __restrict__ C,
           int M, int N, int K, const float* __restrict__ gates, int gstride,
           long zsA, long zsB, long zsBias, long zsC,
           const int* __restrict__ rows_all, const int* __restrict__ cnts)
{
    const int z  = blockIdx.z;
    const int Mz = cnts ? cnts[z] : M;
    const int m0 = blockIdx.y * QM;
    if (m0 >= Mz) return;

    __shared__ __align__(16) float  As [2][QK][QM];
    __shared__ __align__(16) float2 Bs2[2][QK][QN];
    const int tid = threadIdx.x;
    const int tx = tid & 15, ty = tid >> 4;
    const int n0 = blockIdx.x * QN;
    A += (size_t)z * zsA; B += (size_t)z * zsB; C += (size_t)z * zsC;
    const float* bz = bias ? bias + (size_t)z * zsBias : nullptr;
    const int* rows = rows_all ? rows_all + (size_t)z * NT : nullptr;

    const int am = tid >> 1, ak = (tid & 1) * 8;
    const int bk = tid >> 5, bn = (tid & 31) * 4;

    size_t arow;
    {
        int r = m0 + am;
        if (INDA) {
            int rr = (r < Mz) ? r : (Mz - 1);
            arow = (size_t)rows[rr];
        } else {
            arow = (size_t)r;
        }
    }
    const float* Abase = A + arow * (size_t)K;

    u64 acc[4][8];
#pragma unroll
    for (int i = 0; i < 4; i++)
#pragma unroll
        for (int j = 0; j < 8; j++) acc[i][j] = 0ull;

    float4 pa0, pa1;
    float  pb[2][4];
    {
        pa0 = *reinterpret_cast<const float4*>(Abase + ak);
        pa1 = *reinterpret_cast<const float4*>(Abase + ak + 4);
#pragma unroll
        for (int r = 0; r < 2; r++) {
            int kk = bk + r * 8;
#pragma unroll
            for (int j = 0; j < 4; j++) {
                int n = n0 + bn + j;
                pb[r][j] = (n < N) ? B[(size_t)kk * N + n] : 0.f;
            }
        }
    }

    const int ktiles = K >> 4;
    for (int kt = 0; kt < ktiles; kt++) {
        const int sb = kt & 1;
        As[sb][ak + 0][am] = pa0.x; As[sb][ak + 1][am] = pa0.y;
        As[sb][ak + 2][am] = pa0.z; As[sb][ak + 3][am] = pa0.w;
        As[sb][ak + 4][am] = pa1.x; As[sb][ak + 5][am] = pa1.y;
        As[sb][ak + 6][am] = pa1.z; As[sb][ak + 7][am] = pa1.w;
#pragma unroll
        for (int r = 0; r < 2; r++)
#pragma unroll
            for (int j = 0; j < 4; j++)
                Bs2[sb][bk + r * 8][bn + j] = make_float2(pb[r][j], pb[r][j]);
        __syncthreads();

        if (kt + 1 < ktiles) {
            int k0 = (kt + 1) * QK;
            pa0 = *reinterpret_cast<const float4*>(Abase + k0 + ak);
            pa1 = *reinterpret_cast<const float4*>(Abase + k0 + ak + 4);
#pragma unroll
            for (int r = 0; r < 2; r++) {
                int kk = k0 + bk + r * 8;
#pragma unroll
                for (int j = 0; j < 4; j++) {
                    int n = n0 + bn + j;
                    pb[r][j] = (n < N) ? B[(size_t)kk * N + n] : 0.f;
                }
            }
        }

#pragma unroll
        for (int k = 0; k < QK; k++) {
            u64 a[4];
#pragma unroll
            for (int i = 0; i < 4; i++)
                a[i] = *reinterpret_cast<const u64*>(&As[sb][k][ty * 8 + 2 * i]);
            u64 b[8];
#pragma unroll
            for (int j4 = 0; j4 < 4; j4++) {
                ulonglong2 v = *reinterpret_cast<const ulonglong2*>(&Bs2[sb][k][tx * 2 + 32 * j4]);
                b[2 * j4] = v.x; b[2 * j4 + 1] = v.y;
            }
#pragma unroll
            for (int i = 0; i < 4; i++)
#pragma unroll
                for (int j = 0; j < 8; j++)
                    ffma2(acc[i][j], a[i], b[j]);
        }
    }

    float bv[8];
#pragma unroll
    for (int j4 = 0; j4 < 4; j4++) {
        int n = n0 + tx * 2 + 32 * j4;
        bv[2 * j4]     = (bz && n     < N) ? bz[n]     : 0.f;
        bv[2 * j4 + 1] = (bz && n + 1 < N) ? bz[n + 1] : 0.f;
    }

#pragma unroll
    for (int mp = 0; mp < 4; mp++) {
#pragma unroll
        for (int hh = 0; hh < 2; hh++) {
            int m = m0 + ty * 8 + mp * 2 + hh;
            if (m >= Mz) continue;
            float gate = 1.f;
            if (EPI == EPI_GATE_WR) {
                int tok = rows ? rows[m] : m;
                gate = gates[(size_t)tok * gstride + z];
            }
            size_t rowb = (size_t)m * N;
#pragma unroll
            for (int j4 = 0; j4 < 4; j4++) {
                int n = n0 + tx * 2 + 32 * j4;
                u64 t0 = acc[mp][2 * j4], t1 = acc[mp][2 * j4 + 1];
                float v0 = hh ? __uint_as_float((unsigned)(t0 >> 32))
                              : __uint_as_float((unsigned)(t0 & 0xffffffffull));
                float v1 = hh ? __uint_as_float((unsigned)(t1 >> 32))
                              : __uint_as_float((unsigned)(t1 & 0xffffffffull));
                v0 += bv[2 * j4]; v1 += bv[2 * j4 + 1];
                if (EPI == EPI_RELU)    { v0 = fmaxf(v0, 0.f); v1 = fmaxf(v1, 0.f); }
                if (EPI == EPI_GATE_WR) { v0 *= gate; v1 *= gate; }
                size_t o = rowb + n;
                if (n + 1 < N && (o & 1) == 0) {
                    *reinterpret_cast<float2*>(&C[o]) = make_float2(v0, v1);
                } else {
                    if (n < N)     C[o]     = v0;
                    if (n + 1 < N) C[o + 1] = v1;
                }
            }
        }
    }
}

// -------------------- mma.sync bf16x3 LM head ------------------------------
// D[4096, VV] = Ah*Bh^T + Al*Bh^T + Ah*Bl^T, fp32 accum in registers.
// CTA: A tile 128m x K=128 resident in smem (hi+lo); LM_NTILES n-tiles of 64.
// Register-staged B prefetch: next tile's B is LDG'd into 32 regs BEFORE the
// mainloop and committed to smem after the post-mainloop sync, hiding gmem
// latency behind compute. Rows padded to LMS=136 (272B): conflict-free ldmatrix.
__global__ void __launch_bounds__(256, 2)
lmhead_mma_k(const __nv_bfloat16* __restrict__ ah, const __nv_bfloat16* __restrict__ al,
             const __nv_bfloat16* __restrict__ bh, const __nv_bfloat16* __restrict__ bl,
             const float* __restrict__ bias, float* __restrict__ out)
{
    extern __shared__ __align__(16) __nv_bfloat16 sm[];
    __nv_bfloat16* sAh = sm;
    __nv_bfloat16* sAl = sm + 128 * LMS;
    __nv_bfloat16* sBh = sm + 2 * 128 * LMS;
    __nv_bfloat16* sBl = sBh + 64 * LMS;
    const int tid = threadIdx.x;
    const int m0 = blockIdx.x * 128;
    const int nbase = blockIdx.y * LM_NTILES * 64;

    const int brow = tid >> 4, bcol = (tid & 15) * 8;   // B staging coords

    // prefetch B(0) into regs, then A into smem (A LDGs overlap B latency)
    uint4 pbh[4], pbl[4];
#pragma unroll
    for (int i = 0; i < 4; i++) {
        int row = brow + i * 16;
        pbh[i] = *reinterpret_cast<const uint4*>(bh + (size_t)(nbase + row) * CC + bcol);
        pbl[i] = *reinterpret_cast<const uint4*>(bl + (size_t)(nbase + row) * CC + bcol);
    }
#pragma unroll
    for (int i = 0; i < 8; i++) {
        int idx = tid + i * 256; int row = idx >> 4, c = (idx & 15) * 8;
        *reinterpret_cast<uint4*>(sAh + row * LMS + c) =
            *reinterpret_cast<const uint4*>(ah + (size_t)(m0 + row) * CC + c);
        *reinterpret_cast<uint4*>(sAl + row * LMS + c) =
            *reinterpret_cast<const uint4*>(al + (size_t)(m0 + row) * CC + c);
    }
#pragma unroll
    for (int i = 0; i < 4; i++) {
        int row = brow + i * 16;
        *reinterpret_cast<uint4*>(sBh + row * LMS + bcol) = pbh[i];
        *reinterpret_cast<uint4*>(sBl + row * LMS + bcol) = pbl[i];
    }
    __syncthreads();

    const int w = tid >> 5, lane = tid & 31;
    const int wm = w >> 1, wn = w & 1;

    const __nv_bfloat16* Ap[3] = { sAh, sAl, sAh };
    const __nv_bfloat16* Bp[3] = { sBh, sBh, sBl };

    for (int nt = 0; nt < LM_NTILES; nt++) {
        const int n0 = nbase + nt * 64;

        // issue next tile's B loads NOW (consumed after mainloop -> latency hidden)
        if (nt + 1 < LM_NTILES) {
#pragma unroll
            for (int i = 0; i < 4; i++) {
                int row = brow + i * 16;
                pbh[i] = *reinterpret_cast<const uint4*>(bh + (size_t)(n0 + 64 + row) * CC + bcol);
                pbl[i] = *reinterpret_cast<const uint4*>(bl + (size_t)(n0 + 64 + row) * CC + bcol);
            }
        }

        float acc[2][4][4];
#pragma unroll
        for (int mt = 0; mt < 2; mt++)
#pragma unroll
            for (int ntl = 0; ntl < 4; ntl++)
#pragma unroll
                for (int q = 0; q < 4; q++) acc[mt][ntl][q] = 0.f;

#pragma unroll
        for (int pass = 0; pass < 3; pass++) {
            const uint32_t abase = smem_u32(Ap[pass]);
            const uint32_t bbase = smem_u32(Bp[pass]);
#pragma unroll
            for (int ks = 0; ks < 8; ks++) {
                const int k0 = ks * 16;
                uint32_t af[2][4];
#pragma unroll
                for (int mt = 0; mt < 2; mt++) {
                    int row = wm * 32 + mt * 16 + (lane & 15);
                    ldmatrix_x4(af[mt], abase + (uint32_t)(row * LMS + k0 + (lane >> 4) * 8) * 2);
                }
                uint32_t bf[4][2];
#pragma unroll
                for (int ntl = 0; ntl < 4; ntl++) {
                    int nr = wn * 32 + ntl * 8 + (lane & 7);
                    ldmatrix_x2(bf[ntl], bbase + (uint32_t)(nr * LMS + k0 + ((lane >> 3) & 1) * 8) * 2);
                }
#pragma unroll
                for (int mt = 0; mt < 2; mt++)
#pragma unroll
                    for (int ntl = 0; ntl < 4; ntl++)
                        mma16816(acc[mt][ntl], af[mt], bf[ntl]);
            }
        }

        __syncthreads();   // all warps done reading B(nt)

        // commit next tile's B to smem (epilogue below doesn't touch B smem)
        if (nt + 1 < LM_NTILES) {
#pragma unroll
            for (int i = 0; i < 4; i++) {
                int row = brow + i * 16;
                *reinterpret_cast<uint4*>(sBh + row * LMS + bcol) = pbh[i];
                *reinterpret_cast<uint4*>(sBl + row * LMS + bcol) = pbl[i];
            }
        }

        // epilogue: D frag c0,c1 -> (m = lane>>2, n = (lane&3)*2+{0,1}); c2,c3 -> m+8
#pragma unroll
        for (int ntl = 0; ntl < 4; ntl++) {
            int n = n0 + wn * 32 + ntl * 8 + (lane & 3) * 2;
            float b0 = (n     < VV) ? bias[n]     : 0.f;
            float b1 = (n + 1 < VV) ? bias[n + 1] : 0.f;
#pragma unroll
            for (int mt = 0; mt < 2; mt++) {
#pragma unroll
                for (int half = 0; half < 2; half++) {
                    int m = m0 + wm * 32 + mt * 16 + (lane >> 2) + half * 8;
                    float v0 = acc[mt][ntl][half * 2 + 0] + b0;
                    float v1 = acc[mt][ntl][half * 2 + 1] + b1;
                    size_t o = (size_t)m * VV + n;
                    if (n + 1 < VV && (o & 1) == 0) {
                        *reinterpret_cast<float2*>(out + o) = make_float2(v0, v1);
                    } else {
                        if (n     < VV) out[o]     = v0;
                        if (n + 1 < VV) out[o + 1] = v1;
                    }
                }
            }
        }
        __syncthreads();   // B(nt+1) stores visible before next mainloop
    }
}

// -------------------- host orchestration ----------------------------------
extern "C" void kernel_launch(void* const* d_in, const int* in_sizes, int n_in,
                              void* d_out, int out_size)
{
    (void)in_sizes; (void)n_in; (void)out_size;
    const int*   idx  = (const int*)  d_in[0];
    const float* tok  = (const float*)d_in[1];
    const float* pos  = (const float*)d_in[2];
    const float* ln1g = (const float*)d_in[3];
    const float* ln1b = (const float*)d_in[4];
    const float* Wq   = (const float*)d_in[5];
    const float* Wk   = (const float*)d_in[6];
    const float* Wv   = (const float*)d_in[7];
    const float* Wo   = (const float*)d_in[8];
    const float* bo   = (const float*)d_in[9];
    const float* ln2g = (const float*)d_in[10];
    const float* ln2b = (const float*)d_in[11];
    const float* Wr   = (const float*)d_in[12];
    const float* br   = (const float*)d_in[13];
    const float* Wn   = (const float*)d_in[14];
    const float* bn   = (const float*)d_in[15];
    const float* Wsr  = (const float*)d_in[16];
    const float* bsr  = (const float*)d_in[17];
    const float* W1   = (const float*)d_in[18];
    const float* b1   = (const float*)d_in[19];
    const float* W2   = (const float*)d_in[20];
    const float* b2   = (const float*)d_in[21];
    const float* lnfg = (const float*)d_in[22];
    const float* lnfb = (const float*)d_in[23];
    const float* Wlm  = (const float*)d_in[24];
    const float* blm  = (const float*)d_in[25];
    float* out = (float*)d_out;

    float *x, *h, *qkv, *att, *nx, *h1c, *eoc, *gates, *wp;
    int *cnt, *list; int4* slot;
    __nv_bfloat16 *bhp, *blp, *ahp, *alp;
    cudaGetSymbolAddress((void**)&x,     g_x);
    cudaGetSymbolAddress((void**)&h,     g_h);
    cudaGetSymbolAddress((void**)&qkv,   g_qkv);
    cudaGetSymbolAddress((void**)&att,   g_att);
    cudaGetSymbolAddress((void**)&nx,    g_nx);
    cudaGetSymbolAddress((void**)&h1c,   g_h1c);
    cudaGetSymbolAddress((void**)&eoc,   g_eoc);
    cudaGetSymbolAddress((void**)&gates, g_gates);
    cudaGetSymbolAddress((void**)&cnt,   g_cnt);
    cudaGetSymbolAddress((void**)&list,  g_list);
    cudaGetSymbolAddress((void**)&slot,  g_slot);
    cudaGetSymbolAddress((void**)&wp,    g_wpack);
    cudaGetSymbolAddress((void**)&bhp,   g_bh);
    cudaGetSymbolAddress((void**)&blp,   g_bl);
    cudaGetSymbolAddress((void**)&ahp,   g_ah);
    cudaGetSymbolAddress((void**)&alp,   g_al);

    embed_k<<<NT * CC / 256, 256>>>(idx, tok, pos, x);
    pack_qkv_all_k<<<NL * CC * 384 / 256, 256>>>(Wq, Wk, Wv, wp);
    pack_b_k<<<dim3(LM_NPAD / 32, CC / 32), dim3(32, 32)>>>(Wlm, bhp, blp);
    reset_cnt_k<<<1, 32>>>(cnt);                 // layer 0; later layers via combine_ln
    layernorm_k<<<NT, CC>>>(x, ln1g, ln1b, h);

    for (int l = 0; l < NL; l++) {
        sgemm128_k<EPI_BIAS, 0><<<dim3(384 / QN, NT / QM), 256>>>(
            h, wp + (size_t)l * CC * 384, nullptr, qkv, NT, 384, CC, nullptr, 0,
            0, 0, 0, 0, nullptr, nullptr);
        attention_k<<<NT / TT * NH, dim3(32, 32)>>>(qkv, att);
        sgemm_k<EPI_RESID><<<dim3(CC / BN, NT / BM), 256>>>(att, Wo + l * CC * CC,
                                                            bo + l * CC, x, NT, CC, CC);
        router_ln_k<<<NT, CC>>>(x, ln2g + l * CC, ln2b + l * CC,
                                Wr + l * CC * NE, br + l * NE,
                                Wn + l * CC * NE, bn + l * NE,
                                Wsr + l * CC, bsr + l,
                                nx, gates, cnt, list, slot, l);
        sgemm128_k<EPI_RELU, 1><<<dim3(FF / QN, NT / QM, NE), 256>>>(
            nx, W1 + (size_t)l * NE * CC * FF, b1 + (size_t)l * NE * FF, h1c,
            NT, FF, CC, nullptr, 0,
            0, (long)CC * FF, FF, (long)NT * FF, list, cnt);
        sgemm128_k<EPI_GATE_WR, 0><<<dim3(CC / QN, NT / QM, NE), 256>>>(
            h1c, W2 + (size_t)l * NE * FF * CC, b2 + (size_t)l * NE * CC, eoc,
            NT, CC, FF, gates, NE,
            (long)NT * FF, (long)FF * CC, CC, (long)NT * CC, list, cnt);
        const float* gnext = (l + 1 < NL) ? (ln1g + (l + 1) * CC) : lnfg;
        const float* bnext = (l + 1 < NL) ? (ln1b + (l + 1) * CC) : lnfb;
        combine_ln_k<<<NT, CC>>>(x, eoc, slot, gnext, bnext, h, cnt);
    }

    pack_a_k<<<NT * CC / 256, 256>>>(h, ahp, alp);
    cudaFuncSetAttribute(lmhead_mma_k, cudaFuncAttributeMaxDynamicSharedMemorySize, LM_SMEM);
    lmhead_mma_k<<<dim3(NT / 128, LM_NPAD / (64 * LM_NTILES)), 256, LM_SMEM>>>(
        ahp, alp, bhp, blp, blm, out);
}

// round 15
// speedup vs baseline: 1.0843x; 1.0843x over previous
#include <cuda_runtime.h>
#include <cuda_bf16.h>
#include <math.h>
#include <stdint.h>

typedef unsigned long long u64;

#define NT   4096   // B*T
#define CC   128    // n_embed
#define TT   32     // block_size
#define NH   4      // heads
#define HS   32     // head size
#define NE   4      // experts
#define NL   4      // layers
#define VV   50257  // vocab
#define FF   512    // 4*C

#define LM_NPAD 50688                 // >= VV, multiple of 256
#define LMS     136                   // padded k-stride (272B = 17*16B)
#define LM_SMEM (2*128*LMS*2 + 2*64*LMS*2)   // 104448 bytes
#define LM_NTILES 4                   // n-tiles per CTA (A reuse)

// -------------------- scratch (device globals; no allocs allowed) ---------
__device__ float g_x   [NT*CC];
__device__ float g_h   [NT*CC];
__device__ float g_qkv [NT*3*CC];
__device__ float g_att [NT*CC];
__device__ float g_nx  [NT*CC];
__device__ float g_h1c [(size_t)NE*NT*FF];
__device__ float g_eoc [(size_t)NE*NT*CC];
__device__ float g_gates[NT*NE];
__device__ int   g_cnt [NE];
__device__ int   g_list[NE*NT];
__device__ int4  g_slot[NT];
__device__ float g_wpack[(size_t)NL*CC*3*CC];
__device__ __nv_bfloat16 g_bh[(size_t)LM_NPAD*CC];   // Wlm^T hi  [n][k]
__device__ __nv_bfloat16 g_bl[(size_t)LM_NPAD*CC];   // Wlm^T lo
__device__ __nv_bfloat16 g_ah[(size_t)NT*CC];        // h hi
__device__ __nv_bfloat16 g_al[(size_t)NT*CC];        // h lo

// -------------------- baseline-PTX mma / cp.async helpers ------------------
__device__ __forceinline__ uint32_t smem_u32(const void* p){
    uint32_t a;
    asm("{ .reg .u64 t; cvta.to.shared.u64 t, %1; cvt.u32.u64 %0, t; }" : "=r"(a) : "l"(p));
    return a;
}
__device__ __forceinline__ void ldmatrix_x4(uint32_t* r, uint32_t addr){
    asm volatile("ldmatrix.sync.aligned.m8n8.x4.shared.b16 {%0,%1,%2,%3}, [%4];"
                 : "=r"(r[0]),"=r"(r[1]),"=r"(r[2]),"=r"(r[3]) : "r"(addr));
}
__device__ __forceinline__ void ldmatrix_x2(uint32_t* r, uint32_t addr){
    asm volatile("ldmatrix.sync.aligned.m8n8.x2.shared.b16 {%0,%1}, [%2];"
                 : "=r"(r[0]),"=r"(r[1]) : "r"(addr));
}
__device__ __forceinline__ void mma16816(float* c, const uint32_t* a, const uint32_t* b){
    asm volatile("mma.sync.aligned.m16n8k16.row.col.f32.bf16.bf16.f32 "
        "{%0,%1,%2,%3}, {%4,%5,%6,%7}, {%8,%9}, {%0,%1,%2,%3};"
        : "+f"(c[0]),"+f"(c[1]),"+f"(c[2]),"+f"(c[3])
        : "r"(a[0]),"r"(a[1]),"r"(a[2]),"r"(a[3]), "r"(b[0]),"r"(b[1]));
}
__device__ __forceinline__ void cp_async16(uint32_t saddr, const void* gaddr){
    asm volatile("cp.async.cg.shared.global [%0], [%1], 16;" :: "r"(saddr), "l"(gaddr));
}
#define CP_COMMIT() asm volatile("cp.async.commit_group;" ::: "memory")
#define CP_WAIT0()  asm volatile("cp.async.wait_group 0;" ::: "memory")

// -------------------- threefry2x32 (JAX-compatible) -----------------------
__device__ __forceinline__ unsigned rotl32(unsigned v, int r){ return (v<<r)|(v>>(32-r)); }

__device__ void threefry2x32(unsigned k0, unsigned k1, unsigned x0, unsigned x1,
                             unsigned &o0, unsigned &o1)
{
    unsigned ks0=k0, ks1=k1, ks2 = k0 ^ k1 ^ 0x1BD11BDAu;
    x0 += ks0; x1 += ks1;
#define TF_RND(r) { x0 += x1; x1 = rotl32(x1, r); x1 ^= x0; }
    TF_RND(13) TF_RND(15) TF_RND(26) TF_RND(6)
    x0 += ks1; x1 += ks2 + 1u;
    TF_RND(17) TF_RND(29) TF_RND(16) TF_RND(24)
    x0 += ks2; x1 += ks0 + 2u;
    TF_RND(13) TF_RND(15) TF_RND(26) TF_RND(6)
    x0 += ks0; x1 += ks1 + 3u;
    TF_RND(17) TF_RND(29) TF_RND(16) TF_RND(24)
    x0 += ks1; x1 += ks2 + 4u;
    TF_RND(13) TF_RND(15) TF_RND(26) TF_RND(6)
    x0 += ks2; x1 += ks0 + 5u;
#undef TF_RND
    o0 = x0; o1 = x1;
}

__device__ float erfinv_f(float x)
{
    float w = -log1pf(-x*x);
    float p;
    if (w < 5.0f) {
        w = w - 2.5f;
        p =               2.81022636e-08f;
        p = fmaf(p, w,    3.43273939e-07f);
        p = fmaf(p, w,   -3.5233877e-06f);
        p = fmaf(p, w,   -4.39150654e-06f);
        p = fmaf(p, w,    0.00021858087f);
        p = fmaf(p, w,   -0.00125372503f);
        p = fmaf(p, w,   -0.00417768164f);
        p = fmaf(p, w,    0.246640727f);
        p = fmaf(p, w,    1.50140941f);
    } else {
        w = sqrtf(w) - 3.0f;
        p =              -0.000200214257f;
        p = fmaf(p, w,    0.000100950558f);
        p = fmaf(p, w,    0.00134934322f);
        p = fmaf(p, w,   -0.00367342844f);
        p = fmaf(p, w,    0.00573950773f);
        p = fmaf(p, w,   -0.0076224613f);
        p = fmaf(p, w,    0.00943887047f);
        p = fmaf(p, w,    1.00167406f);
        p = fmaf(p, w,    2.83297682f);
    }
    return p * x;
}

__device__ float jax_normal_elem(unsigned i)
{
    unsigned y0, y1;
    threefry2x32(0u, 42u, 0u, i, y0, y1);
    unsigned bits = y0 ^ y1;
    float f  = __uint_as_float((bits >> 9) | 0x3f800000u) - 1.0f;
    const float lo = -0.99999994f;
    float u = fmaxf(lo, fmaf(f, 2.0f, lo));
    return 1.41421356f * erfinv_f(u);
}

// -------------------- small kernels ---------------------------------------
__global__ void embed_k(const int* __restrict__ idx, const float* __restrict__ tok,
                        const float* __restrict__ pos, float* __restrict__ x)
{
    int gid = blockIdx.x * blockDim.x + threadIdx.x;
    int r = gid >> 7, c = gid & 127;
    int t = r & (TT - 1);
    x[gid] = tok[idx[r] * CC + c] + pos[t * CC + c];
}

__global__ void layernorm_k(const float* __restrict__ x, const float* __restrict__ g,
                            const float* __restrict__ b, float* __restrict__ out)
{
    int row = blockIdx.x, c = threadIdx.x;
    __shared__ float red[CC];
    float v = x[row * CC + c];
    red[c] = v; __syncthreads();
    for (int s = 64; s > 0; s >>= 1) { if (c < s) red[c] += red[c + s]; __syncthreads(); }
    float mean = red[0] * (1.0f / CC);
    __syncthreads();
    float d = v - mean;
    red[c] = d * d; __syncthreads();
    for (int s = 64; s > 0; s >>= 1) { if (c < s) red[c] += red[c + s]; __syncthreads(); }
    float var = red[0] * (1.0f / CC);
    out[row * CC + c] = d / sqrtf(var + 1e-5f) * g[c] + b[c];
}

__global__ void pack_qkv_all_k(const float* __restrict__ Wq, const float* __restrict__ Wk,
                               const float* __restrict__ Wv, float* __restrict__ wp)
{
    int gid = blockIdx.x * blockDim.x + threadIdx.x;   // NL*CC*384
    int l   = gid / (CC * 384);
    int rem = gid % (CC * 384);
    int c = rem / 384, j = rem % 384;
    size_t lw = (size_t)l * NH * CC * HS;
    const float* W = (j < 128) ? (Wq + lw) : (j < 256 ? (Wk + lw) : (Wv + lw));
    int jj = j & 127;
    int hh = jj >> 5, dd = jj & 31;
    wp[gid] = W[(hh * CC + c) * HS + dd];
}

// pack Wlm -> transposed bf16 hi/lo: bpack[n][k] = bf16split(Wlm[k][n])
__global__ void pack_b_k(const float* __restrict__ Wlm,
                         __nv_bfloat16* __restrict__ bh, __nv_bfloat16* __restrict__ bl)
{
    __shared__ float s[32][33];
    int n0 = blockIdx.x * 32, k0 = blockIdx.y * 32;
    int tx = threadIdx.x, ty = threadIdx.y;
    int n = n0 + tx;
    s[ty][tx] = (n < VV) ? Wlm[(size_t)(k0 + ty) * VV + n] : 0.f;
    __syncthreads();
    float f = s[tx][ty];
    __nv_bfloat16 hi = __float2bfloat16(f);
    float lo = f - __bfloat162float(hi);
    size_t o = (size_t)(n0 + ty) * CC + k0 + tx;
    bh[o] = hi;
    bl[o] = __float2bfloat16(lo);
}

__global__ void pack_a_k(const float* __restrict__ h,
                         __nv_bfloat16* __restrict__ ah, __nv_bfloat16* __restrict__ al)
{
    int i = blockIdx.x * blockDim.x + threadIdx.x;
    float f = h[i];
    __nv_bfloat16 hi = __float2bfloat16(f);
    ah[i] = hi;
    al[i] = __float2bfloat16(f - __bfloat162float(hi));
}

__global__ void attention_k(const float* __restrict__ qkv, float* __restrict__ att)
{
    int b = blockIdx.x >> 2, h = blockIdx.x & 3;
    int t = threadIdx.y, s = threadIdx.x;
    __shared__ float qs[TT][HS+1], ks[TT][HS+1], vs[TT][HS+1], ws[TT][TT+1];
    int base = (b * TT + t) * (3 * CC) + h * HS;
    qs[t][s] = qkv[base + s];
    ks[t][s] = qkv[base + CC + s];
    vs[t][s] = qkv[base + 2 * CC + s];
    __syncthreads();
    const float NEG_INF = __int_as_float(0xff800000);
    float w;
    if (s <= t) {
        float acc = 0.f;
#pragma unroll
        for (int d = 0; d < HS; d++) acc = fmaf(qs[t][d], ks[s][d], acc);
        w = acc * 0.08838834764831845f;
    } else w = NEG_INF;
    float m = w;
#pragma unroll
    for (int o = 16; o; o >>= 1) m = fmaxf(m, __shfl_xor_sync(0xffffffffu, m, o));
    float e = (s <= t) ? expf(w - m) : 0.f;
    float sum = e;
#pragma unroll
    for (int o = 16; o; o >>= 1) sum += __shfl_xor_sync(0xffffffffu, sum, o);
    ws[t][s] = e / sum;
    __syncthreads();
    float acc = 0.f;
#pragma unroll
    for (int k = 0; k < TT; k++) acc = fmaf(ws[t][k], vs[k][s], acc);
    att[(b * TT + t) * CC + h * HS + s] = acc;
}

__global__ void reset_cnt_k(int* __restrict__ cnt)
{
    if (threadIdx.x < NE) cnt[threadIdx.x] = 0;
}

__global__ void router_ln_k(const float* __restrict__ x,
                            const float* __restrict__ g2, const float* __restrict__ b2,
                            const float* __restrict__ Wr, const float* __restrict__ br,
                            const float* __restrict__ Wn, const float* __restrict__ bn,
                            const float* __restrict__ Ws, const float* __restrict__ bs,
                            float* __restrict__ nx, float* __restrict__ gates,
                            int* __restrict__ cnt, int* __restrict__ list,
                            int4* __restrict__ slot, int layer)
{
    int row = blockIdx.x, c = threadIdx.x;
    __shared__ float red[9][CC];
    float xv = x[row * CC + c];
    red[0][c] = xv; __syncthreads();
    for (int s = 64; s > 0; s >>= 1) { if (c < s) red[0][c] += red[0][c + s]; __syncthreads(); }
    float mean = red[0][0] * (1.0f / CC);
    __syncthreads();
    float d = xv - mean;
    red[0][c] = d * d; __syncthreads();
    for (int s = 64; s > 0; s >>= 1) { if (c < s) red[0][c] += red[0][c + s]; __syncthreads(); }
    float var = red[0][0] * (1.0f / CC);
    __syncthreads();
    float v = d / sqrtf(var + 1e-5f) * g2[c] + b2[c];
    nx[row * CC + c] = v;
#pragma unroll
    for (int e = 0; e < NE; e++) {
        red[e][c]     = v * Wr[c * NE + e];
        red[4 + e][c] = v * Wn[c * NE + e];
    }
    red[8][c] = v * Ws[c];
    __syncthreads();
    for (int st = 64; st > 0; st >>= 1) {
        if (c < st) {
#pragma unroll
            for (int j = 0; j < 9; j++) red[j][c] += red[j][c + st];
        }
        __syncthreads();
    }
    if (c == 0) {
        float noisy[NE];
#pragma unroll
        for (int e = 0; e < NE; e++) {
            float logit = red[e][0] + br[e];
            float nl    = red[4 + e][0] + bn[e];
            float sp    = fmaxf(nl, 0.f) + log1pf(expf(-fabsf(nl)));
            unsigned i  = ((unsigned)(layer * NT + row)) * NE + e;
            noisy[e]    = logit + jax_normal_elem(i) * sp;
        }
        int i1 = 0;
        for (int e = 1; e < NE; e++) if (noisy[e] > noisy[i1]) i1 = e;
        int i2 = -1;
        for (int e = 0; e < NE; e++) if (e != i1 && (i2 < 0 || noisy[e] > noisy[i2])) i2 = e;
        float mx = noisy[i1];
        float gv[NE], gsum = 0.f;
#pragma unroll
        for (int e = 0; e < NE; e++) {
            gv[e] = (e == i1 || e == i2) ? expf(noisy[e] - mx) : 0.f;
            gsum += gv[e];
        }
#pragma unroll
        for (int e = 0; e < NE; e++) gates[row * NE + e] = gv[e] / gsum;
        int skipped = (red[8][0] + bs[0] > 0.f);
        if (!skipped) {
            int ea = i1 < i2 ? i1 : i2;
            int eb = i1 < i2 ? i2 : i1;
            int pa = atomicAdd(&cnt[ea], 1); list[ea * NT + pa] = row;
            int pb = atomicAdd(&cnt[eb], 1); list[eb * NT + pb] = row;
            slot[row] = make_int4(ea, pa, eb, pb);
        } else {
            slot[row] = make_int4(-1, 0, -1, 0);
        }
    }
}

// fused combine + next layernorm; also zeroes cnt for the NEXT layer's router
__global__ void combine_ln_k(float* __restrict__ x, const float* __restrict__ eoc,
                             const int4* __restrict__ slot,
                             const float* __restrict__ g, const float* __restrict__ b,
                             float* __restrict__ hout, int* __restrict__ cnt)
{
    int row = blockIdx.x, c = threadIdx.x;
    __shared__ float red[CC];
    int4 s = slot[row];
    float v = x[row * CC + c];
    if (s.x >= 0)
        v += eoc[((size_t)s.x * NT + s.y) * CC + c]
           + eoc[((size_t)s.z * NT + s.w) * CC + c];
    x[row * CC + c] = v;
    if (row == 0 && c < NE) cnt[c] = 0;      // reset for next layer's router
    red[c] = v; __syncthreads();
    for (int st = 64; st > 0; st >>= 1) { if (c < st) red[c] += red[c + st]; __syncthreads(); }
    float mean = red[0] * (1.0f / CC);
    __syncthreads();
    float d = v - mean;
    red[c] = d * d; __syncthreads();
    for (int st = 64; st > 0; st >>= 1) { if (c < st) red[c] += red[c + st]; __syncthreads(); }
    float var = red[0] * (1.0f / CC);
    hout[row * CC + c] = d / sqrtf(var + 1e-5f) * g[c] + b[c];
}

// -------------------- FFMA2 helper ----------------------------------------
__device__ __forceinline__ void ffma2(u64 &d, u64 a, u64 b)
{
    asm("fma.rn.f32x2 %0, %1, %2, %0;" : "+l"(d) : "l"(a), "l"(b));
}

enum { EPI_BIAS = 0, EPI_RELU = 1, EPI_RESID = 2, EPI_GATE_WR = 3 };

// -------------------- 64x64 SGEMM (proj only) ------------------------------
#define BM 64
#define BN 64
#define BK 16

template<int EPI>
__global__ void __launch_bounds__(256, 4)
sgemm_k(const float* __restrict__ A, const float* __restrict__ B,
        const float* __restrict__ bias, float* __restrict__ C,
        int M, int N, int K)
{
    __shared__ float2 As2[BK][BM];
    __shared__ float  Bs [BK][BN];
    int tid = threadIdx.x;
    int n0 = blockIdx.x * BN, m0 = blockIdx.y * BM;
    int tx = tid & 15, ty = tid >> 4;
    int am = tid >> 2,  ak = (tid & 3) * 4;
    int bk = tid >> 4,  bn = (tid & 15) * 4;

    u64 acc[4][2];
#pragma unroll
    for (int i = 0; i < 4; i++) { acc[i][0] = 0ull; acc[i][1] = 0ull; }

    for (int k0 = 0; k0 < K; k0 += BK) {
        float4 av = *reinterpret_cast<const float4*>(&A[(size_t)(m0 + am) * K + k0 + ak]);
        As2[ak + 0][am] = make_float2(av.x, av.x);
        As2[ak + 1][am] = make_float2(av.y, av.y);
        As2[ak + 2][am] = make_float2(av.z, av.z);
        As2[ak + 3][am] = make_float2(av.w, av.w);
        const float* Brow = &B[(size_t)(k0 + bk) * N + n0 + bn];
        Bs[bk][bn + 0] = Brow[0]; Bs[bk][bn + 1] = Brow[1];
        Bs[bk][bn + 2] = Brow[2]; Bs[bk][bn + 3] = Brow[3];
        __syncthreads();
#pragma unroll
        for (int k = 0; k < BK; k++) {
            u64 a[4];
#pragma unroll
            for (int i = 0; i < 4; i++)
                a[i] = *reinterpret_cast<const u64*>(&As2[k][ty * 4 + i]);
            ulonglong2 bv = *reinterpret_cast<const ulonglong2*>(&Bs[k][tx * 4]);
#pragma unroll
            for (int i = 0; i < 4; i++) {
                ffma2(acc[i][0], a[i], bv.x);
                ffma2(acc[i][1], a[i], bv.y);
            }
        }
        __syncthreads();
    }

#pragma unroll
    for (int i = 0; i < 4; i++) {
        int m = m0 + ty * 4 + i;
#pragma unroll
        for (int p = 0; p < 2; p++) {
            float vlo = __uint_as_float((unsigned)(acc[i][p] & 0xffffffffull));
            float vhi = __uint_as_float((unsigned)(acc[i][p] >> 32));
#pragma unroll
            for (int q = 0; q < 2; q++) {
                int n = n0 + tx * 4 + p * 2 + q;
                float val = (q == 0 ? vlo : vhi) + (bias ? bias[n] : 0.f);
                size_t o = (size_t)m * N + n;
                if      (EPI == EPI_BIAS)  C[o] = val;
                else if (EPI == EPI_RESID) C[o] = C[o] + val;
            }
        }
    }
}

// -------------------- 128x128 SGEMM (QKV / MoE compact) --------------------
#define QM 128
#define QN 128
#define QK 16

template<int EPI, int INDA>
__global__ void __launch_bounds__(256, 2)
sgemm128_k(const float* __restrict__ A, const float* __restrict__ B,
           const float* __restrict__ bias, float* __restrict__ C,
           int M, int N, int K, const float* __restrict__ gates, int gstride,
           long zsA, long zsB, long zsBias, long zsC,
           const int* __restrict__ rows_all, const int* __restrict__ cnts)
{
    const int z  = blockIdx.z;
    const int Mz = cnts ? cnts[z] : M;
    const int m0 = blockIdx.y * QM;
    if (m0 >= Mz) return;

    __shared__ __align__(16) float  As [2][QK][QM];
    __shared__ __align__(16) float2 Bs2[2][QK][QN];
    const int tid = threadIdx.x;
    const int tx = tid & 15, ty = tid >> 4;
    const int n0 = blockIdx.x * QN;
    A += (size_t)z * zsA; B += (size_t)z * zsB; C += (size_t)z * zsC;
    const float* bz = bias ? bias + (size_t)z * zsBias : nullptr;
    const int* rows = rows_all ? rows_all + (size_t)z * NT : nullptr;

    const int am = tid >> 1, ak = (tid & 1) * 8;
    const int bk = tid >> 5, bn = (tid & 31) * 4;

    size_t arow;
    {
        int r = m0 + am;
        if (INDA) {
            int rr = (r < Mz) ? r : (Mz - 1);
            arow = (size_t)rows[rr];
        } else {
            arow = (size_t)r;
        }
    }
    const float* Abase = A + arow * (size_t)K;

    u64 acc[4][8];
#pragma unroll
    for (int i = 0; i < 4; i++)
#pragma unroll
        for (int j = 0; j < 8; j++) acc[i][j] = 0ull;

    float4 pa0, pa1;
    float  pb[2][4];
    {
        pa0 = *reinterpret_cast<const float4*>(Abase + ak);
        pa1 = *reinterpret_cast<const float4*>(Abase + ak + 4);
#pragma unroll
        for (int r = 0; r < 2; r++) {
            int kk = bk + r * 8;
#pragma unroll
            for (int j = 0; j < 4; j++) {
                int n = n0 + bn + j;
                pb[r][j] = (n < N) ? B[(size_t)kk * N + n] : 0.f;
            }
        }
    }

    const int ktiles = K >> 4;
    for (int kt = 0; kt < ktiles; kt++) {
        const int sb = kt & 1;
        As[sb][ak + 0][am] = pa0.x; As[sb][ak + 1][am] = pa0.y;
        As[sb][ak + 2][am] = pa0.z; As[sb][ak + 3][am] = pa0.w;
        As[sb][ak + 4][am] = pa1.x; As[sb][ak + 5][am] = pa1.y;
        As[sb][ak + 6][am] = pa1.z; As[sb][ak + 7][am] = pa1.w;
#pragma unroll
        for (int r = 0; r < 2; r++)
#pragma unroll
            for (int j = 0; j < 4; j++)
                Bs2[sb][bk + r * 8][bn + j] = make_float2(pb[r][j], pb[r][j]);
        __syncthreads();

        if (kt + 1 < ktiles) {
            int k0 = (kt + 1) * QK;
            pa0 = *reinterpret_cast<const float4*>(Abase + k0 + ak);
            pa1 = *reinterpret_cast<const float4*>(Abase + k0 + ak + 4);
#pragma unroll
            for (int r = 0; r < 2; r++) {
                int kk = k0 + bk + r * 8;
#pragma unroll
                for (int j = 0; j < 4; j++) {
                    int n = n0 + bn + j;
                    pb[r][j] = (n < N) ? B[(size_t)kk * N + n] : 0.f;
                }
            }
        }

#pragma unroll
        for (int k = 0; k < QK; k++) {
            u64 a[4];
#pragma unroll
            for (int i = 0; i < 4; i++)
                a[i] = *reinterpret_cast<const u64*>(&As[sb][k][ty * 8 + 2 * i]);
            u64 b[8];
#pragma unroll
            for (int j4 = 0; j4 < 4; j4++) {
                ulonglong2 v = *reinterpret_cast<const ulonglong2*>(&Bs2[sb][k][tx * 2 + 32 * j4]);
                b[2 * j4] = v.x; b[2 * j4 + 1] = v.y;
            }
#pragma unroll
            for (int i = 0; i < 4; i++)
#pragma unroll
                for (int j = 0; j < 8; j++)
                    ffma2(acc[i][j], a[i], b[j]);
        }
    }

    float bv[8];
#pragma unroll
    for (int j4 = 0; j4 < 4; j4++) {
        int n = n0 + tx * 2 + 32 * j4;
        bv[2 * j4]     = (bz && n     < N) ? bz[n]     : 0.f;
        bv[2 * j4 + 1] = (bz && n + 1 < N) ? bz[n + 1] : 0.f;
    }

#pragma unroll
    for (int mp = 0; mp < 4; mp++) {
#pragma unroll
        for (int hh = 0; hh < 2; hh++) {
            int m = m0 + ty * 8 + mp * 2 + hh;
            if (m >= Mz) continue;
            float gate = 1.f;
            if (EPI == EPI_GATE_WR) {
                int tok = rows ? rows[m] : m;
                gate = gates[(size_t)tok * gstride + z];
            }
            size_t rowb = (size_t)m * N;
#pragma unroll
            for (int j4 = 0; j4 < 4; j4++) {
                int n = n0 + tx * 2 + 32 * j4;
                u64 t0 = acc[mp][2 * j4], t1 = acc[mp][2 * j4 + 1];
                float v0 = hh ? __uint_as_float((unsigned)(t0 >> 32))
                              : __uint_as_float((unsigned)(t0 & 0xffffffffull));
                float v1 = hh ? __uint_as_float((unsigned)(t1 >> 32))
                              : __uint_as_float((unsigned)(t1 & 0xffffffffull));
                v0 += bv[2 * j4]; v1 += bv[2 * j4 + 1];
                if (EPI == EPI_RELU)    { v0 = fmaxf(v0, 0.f); v1 = fmaxf(v1, 0.f); }
                if (EPI == EPI_GATE_WR) { v0 *= gate; v1 *= gate; }
                size_t o = rowb + n;
                if (n + 1 < N && (o & 1) == 0) {
                    *reinterpret_cast<float2*>(&C[o]) = make_float2(v0, v1);
                } else {
                    if (n < N)     C[o]     = v0;
                    if (n + 1 < N) C[o + 1] = v1;
                }
            }
        }
    }
}

// -------------------- mma.sync bf16x3 LM head ------------------------------
// D[4096, VV] = Ah*Bh^T + Al*Bh^T + Ah*Bl^T, fp32 accum in registers.
// CTA: A tile 128m x K=128 resident in smem (hi+lo); LM_NTILES n-tiles of 64.
// Mainloop = R13 form (3 passes, fragments reloaded per pass; NO long-lived
// prefetch registers — they regressed in R12/R14). Next tile's B is prefetched
// with cp.async (zero register cost) after the post-mainloop sync, overlapping
// the epilogue's STG work; wait_group before the next mainloop.
__global__ void __launch_bounds__(256, 2)
lmhead_mma_k(const __nv_bfloat16* __restrict__ ah, const __nv_bfloat16* __restrict__ al,
             const __nv_bfloat16* __restrict__ bh, const __nv_bfloat16* __restrict__ bl,
             const float* __restrict__ bias, float* __restrict__ out)
{
    extern __shared__ __align__(16) __nv_bfloat16 sm[];
    __nv_bfloat16* sAh = sm;
    __nv_bfloat16* sAl = sm + 128 * LMS;
    __nv_bfloat16* sBh = sm + 2 * 128 * LMS;
    __nv_bfloat16* sBl = sBh + 64 * LMS;
    const int tid = threadIdx.x;
    const int m0 = blockIdx.x * 128;
    const int nbase = blockIdx.y * LM_NTILES * 64;

    const int brow = tid >> 4, bcol = (tid & 15) * 8;   // B staging coords
    const uint32_t sBh_u = smem_u32(sBh), sBl_u = smem_u32(sBl);

    // B(0) via cp.async (overlaps A's LDG+STS below), A direct
#pragma unroll
    for (int i = 0; i < 4; i++) {
        int row = brow + i * 16;
        cp_async16(sBh_u + (uint32_t)(row * LMS + bcol) * 2,
                   bh + (size_t)(nbase + row) * CC + bcol);
        cp_async16(sBl_u + (uint32_t)(row * LMS + bcol) * 2,
                   bl + (size_t)(nbase + row) * CC + bcol);
    }
    CP_COMMIT();
#pragma unroll
    for (int i = 0; i < 8; i++) {
        int idx = tid + i * 256; int row = idx >> 4, c = (idx & 15) * 8;
        *reinterpret_cast<uint4*>(sAh + row * LMS + c) =
            *reinterpret_cast<const uint4*>(ah + (size_t)(m0 + row) * CC + c);
        *reinterpret_cast<uint4*>(sAl + row * LMS + c) =
            *reinterpret_cast<const uint4*>(al + (size_t)(m0 + row) * CC + c);
    }
    CP_WAIT0();
    __syncthreads();

    const int w = tid >> 5, lane = tid & 31;
    const int wm = w >> 1, wn = w & 1;

    const __nv_bfloat16* Ap[3] = { sAh, sAl, sAh };
    const __nv_bfloat16* Bp[3] = { sBh, sBh, sBl };

    for (int nt = 0; nt < LM_NTILES; nt++) {
        const int n0 = nbase + nt * 64;

        float acc[2][4][4];
#pragma unroll
        for (int mt = 0; mt < 2; mt++)
#pragma unroll
            for (int ntl = 0; ntl < 4; ntl++)
#pragma unroll
                for (int q = 0; q < 4; q++) acc[mt][ntl][q] = 0.f;

#pragma unroll
        for (int pass = 0; pass < 3; pass++) {
            const uint32_t abase = smem_u32(Ap[pass]);
            const uint32_t bbase = smem_u32(Bp[pass]);
#pragma unroll
            for (int ks = 0; ks < 8; ks++) {
                const int k0 = ks * 16;
                uint32_t af[2][4];
#pragma unroll
                for (int mt = 0; mt < 2; mt++) {
                    int row = wm * 32 + mt * 16 + (lane & 15);
                    ldmatrix_x4(af[mt], abase + (uint32_t)(row * LMS + k0 + (lane >> 4) * 8) * 2);
                }
                uint32_t bf[4][2];
#pragma unroll
                for (int ntl = 0; ntl < 4; ntl++) {
                    int nr = wn * 32 + ntl * 8 + (lane & 7);
                    ldmatrix_x2(bf[ntl], bbase + (uint32_t)(nr * LMS + k0 + ((lane >> 3) & 1) * 8) * 2);
                }
#pragma unroll
                for (int mt = 0; mt < 2; mt++)
#pragma unroll
                    for (int ntl = 0; ntl < 4; ntl++)
                        mma16816(acc[mt][ntl], af[mt], bf[ntl]);
            }
        }

        __syncthreads();   // all warps done reading B(nt)

        // cp.async prefetch of B(nt+1): zero registers, overlaps epilogue STGs
        if (nt + 1 < LM_NTILES) {
#pragma unroll
            for (int i = 0; i < 4; i++) {
                int row = brow + i * 16;
                cp_async16(sBh_u + (uint32_t)(row * LMS + bcol) * 2,
                           bh + (size_t)(n0 + 64 + row) * CC + bcol);
                cp_async16(sBl_u + (uint32_t)(row * LMS + bcol) * 2,
                           bl + (size_t)(n0 + 64 + row) * CC + bcol);
            }
            CP_COMMIT();
        }

        // epilogue: D frag c0,c1 -> (m = lane>>2, n = (lane&3)*2+{0,1}); c2,c3 -> m+8
#pragma unroll
        for (int ntl = 0; ntl < 4; ntl++) {
            int n = n0 + wn * 32 + ntl * 8 + (lane & 3) * 2;
            float b0 = (n     < VV) ? bias[n]     : 0.f;
            float b1 = (n + 1 < VV) ? bias[n + 1] : 0.f;
#pragma unroll
            for (int mt = 0; mt < 2; mt++) {
#pragma unroll
                for (int half = 0; half < 2; half++) {
                    int m = m0 + wm * 32 + mt * 16 + (lane >> 2) + half * 8;
                    float v0 = acc[mt][ntl][half * 2 + 0] + b0;
                    float v1 = acc[mt][ntl][half * 2 + 1] + b1;
                    size_t o = (size_t)m * VV + n;
                    if (n + 1 < VV && (o & 1) == 0) {
                        *reinterpret_cast<float2*>(out + o) = make_float2(v0, v1);
                    } else {
                        if (n     < VV) out[o]     = v0;
                        if (n + 1 < VV) out[o + 1] = v1;
                    }
                }
            }
        }
        if (nt + 1 < LM_NTILES) CP_WAIT0();
        __syncthreads();   // B(nt+1) visible before next mainloop
    }
}

// -------------------- host orchestration ----------------------------------
extern "C" void kernel_launch(void* const* d_in, const int* in_sizes, int n_in,
                              void* d_out, int out_size)
{
    (void)in_sizes; (void)n_in; (void)out_size;
    const int*   idx  = (const int*)  d_in[0];
    const float* tok  = (const float*)d_in[1];
    const float* pos  = (const float*)d_in[2];
    const float* ln1g = (const float*)d_in[3];
    const float* ln1b = (const float*)d_in[4];
    const float* Wq   = (const float*)d_in[5];
    const float* Wk   = (const float*)d_in[6];
    const float* Wv   = (const float*)d_in[7];
    const float* Wo   = (const float*)d_in[8];
    const float* bo   = (const float*)d_in[9];
    const float* ln2g = (const float*)d_in[10];
    const float* ln2b = (const float*)d_in[11];
    const float* Wr   = (const float*)d_in[12];
    const float* br   = (const float*)d_in[13];
    const float* Wn   = (const float*)d_in[14];
    const float* bn   = (const float*)d_in[15];
    const float* Wsr  = (const float*)d_in[16];
    const float* bsr  = (const float*)d_in[17];
    const float* W1   = (const float*)d_in[18];
    const float* b1   = (const float*)d_in[19];
    const float* W2   = (const float*)d_in[20];
    const float* b2   = (const float*)d_in[21];
    const float* lnfg = (const float*)d_in[22];
    const float* lnfb = (const float*)d_in[23];
    const float* Wlm  = (const float*)d_in[24];
    const float* blm  = (const float*)d_in[25];
    float* out = (float*)d_out;

    float *x, *h, *qkv, *att, *nx, *h1c, *eoc, *gates, *wp;
    int *cnt, *list; int4* slot;
    __nv_bfloat16 *bhp, *blp, *ahp, *alp;
    cudaGetSymbolAddress((void**)&x,     g_x);
    cudaGetSymbolAddress((void**)&h,     g_h);
    cudaGetSymbolAddress((void**)&qkv,   g_qkv);
    cudaGetSymbolAddress((void**)&att,   g_att);
    cudaGetSymbolAddress((void**)&nx,    g_nx);
    cudaGetSymbolAddress((void**)&h1c,   g_h1c);
    cudaGetSymbolAddress((void**)&eoc,   g_eoc);
    cudaGetSymbolAddress((void**)&gates, g_gates);
    cudaGetSymbolAddress((void**)&cnt,   g_cnt);
    cudaGetSymbolAddress((void**)&list,  g_list);
    cudaGetSymbolAddress((void**)&slot,  g_slot);
    cudaGetSymbolAddress((void**)&wp,    g_wpack);
    cudaGetSymbolAddress((void**)&bhp,   g_bh);
    cudaGetSymbolAddress((void**)&blp,   g_bl);
    cudaGetSymbolAddress((void**)&ahp,   g_ah);
    cudaGetSymbolAddress((void**)&alp,   g_al);

    embed_k<<<NT * CC / 256, 256>>>(idx, tok, pos, x);
    pack_qkv_all_k<<<NL * CC * 384 / 256, 256>>>(Wq, Wk, Wv, wp);
    pack_b_k<<<dim3(LM_NPAD / 32, CC / 32), dim3(32, 32)>>>(Wlm, bhp, blp);
    reset_cnt_k<<<1, 32>>>(cnt);                 // layer 0; later layers via combine_ln
    layernorm_k<<<NT, CC>>>(x, ln1g, ln1b, h);

    for (int l = 0; l < NL; l++) {
        sgemm128_k<EPI_BIAS, 0><<<dim3(384 / QN, NT / QM), 256>>>(
            h, wp + (size_t)l * CC * 384, nullptr, qkv, NT, 384, CC, nullptr, 0,
            0, 0, 0, 0, nullptr, nullptr);
        attention_k<<<NT / TT * NH, dim3(32, 32)>>>(qkv, att);
        sgemm_k<EPI_RESID><<<dim3(CC / BN, NT / BM), 256>>>(att, Wo + l * CC * CC,
                                                            bo + l * CC, x, NT, CC, CC);
        router_ln_k<<<NT, CC>>>(x, ln2g + l * CC, ln2b + l * CC,
                                Wr + l * CC * NE, br + l * NE,
                                Wn + l * CC * NE, bn + l * NE,
                                Wsr + l * CC, bsr + l,
                                nx, gates, cnt, list, slot, l);
        sgemm128_k<EPI_RELU, 1><<<dim3(FF / QN, NT / QM, NE), 256>>>(
            nx, W1 + (size_t)l * NE * CC * FF, b1 + (size_t)l * NE * FF, h1c,
            NT, FF, CC, nullptr, 0,
            0, (long)CC * FF, FF, (long)NT * FF, list, cnt);
        sgemm128_k<EPI_GATE_WR, 0><<<dim3(CC / QN, NT / QM, NE), 256>>>(
            h1c, W2 + (size_t)l * NE * FF * CC, b2 + (size_t)l * NE * CC, eoc,
            NT, CC, FF, gates, NE,
            (long)NT * FF, (long)FF * CC, CC, (long)NT * CC, list, cnt);
        const float* gnext = (l + 1 < NL) ? (ln1g + (l + 1) * CC) : lnfg;
        const float* bnext = (l + 1 < NL) ? (ln1b + (l + 1) * CC) : lnfb;
        combine_ln_k<<<NT, CC>>>(x, eoc, slot, gnext, bnext, h, cnt);
    }

    pack_a_k<<<NT * CC / 256, 256>>>(h, ahp, alp);
    cudaFuncSetAttribute(lmhead_mma_k, cudaFuncAttributeMaxDynamicSharedMemorySize, LM_SMEM);
    lmhead_mma_k<<<dim3(NT / 128, LM_NPAD / (64 * LM_NTILES)), 256, LM_SMEM>>>(
        ahp, alp, bhp, blp, blm, out);
}

// round 16
// speedup vs baseline: 1.0862x; 1.0018x over previous
#include <cuda_runtime.h>
#include <cuda_bf16.h>
#include <math.h>
#include <stdint.h>

typedef unsigned long long u64;

#define NT   4096   // B*T
#define CC   128    // n_embed
#define TT   32     // block_size
#define NH   4      // heads
#define HS   32     // head size
#define NE   4      // experts
#define NL   4      // layers
#define VV   50257  // vocab
#define FF   512    // 4*C

#define LM_NPAD 50688                 // >= VV, multiple of 512
#define LMS     136                   // padded k-stride (272B = 17*16B)
#define LM_SMEM (2*128*LMS*2 + 2*64*LMS*2)   // 104448 bytes
#define LM_NTILES 8                   // n-tiles per CTA (A reuse)

// -------------------- scratch (device globals; no allocs allowed) ---------
__device__ float g_x   [NT*CC];
__device__ float g_h   [NT*CC];
__device__ float g_qkv [NT*3*CC];
__device__ float g_att [NT*CC];
__device__ float g_nx  [NT*CC];
__device__ float g_h1c [(size_t)NE*NT*FF];
__device__ float g_eoc [(size_t)NE*NT*CC];
__device__ float g_gates[NT*NE];
__device__ int   g_cnt [NE];
__device__ int   g_list[NE*NT];
__device__ int4  g_slot[NT];
__device__ float g_wpack[(size_t)NL*CC*3*CC];
__device__ __nv_bfloat16 g_bh[(size_t)LM_NPAD*CC];   // Wlm^T hi  [n][k]
__device__ __nv_bfloat16 g_bl[(size_t)LM_NPAD*CC];   // Wlm^T lo
__device__ __nv_bfloat16 g_ah[(size_t)NT*CC];        // h hi
__device__ __nv_bfloat16 g_al[(size_t)NT*CC];        // h lo

// -------------------- baseline-PTX mma / cp.async helpers ------------------
__device__ __forceinline__ uint32_t smem_u32(const void* p){
    uint32_t a;
    asm("{ .reg .u64 t; cvta.to.shared.u64 t, %1; cvt.u32.u64 %0, t; }" : "=r"(a) : "l"(p));
    return a;
}
__device__ __forceinline__ void ldmatrix_x4(uint32_t* r, uint32_t addr){
    asm volatile("ldmatrix.sync.aligned.m8n8.x4.shared.b16 {%0,%1,%2,%3}, [%4];"
                 : "=r"(r[0]),"=r"(r[1]),"=r"(r[2]),"=r"(r[3]) : "r"(addr));
}
__device__ __forceinline__ void ldmatrix_x2(uint32_t* r, uint32_t addr){
    asm volatile("ldmatrix.sync.aligned.m8n8.x2.shared.b16 {%0,%1}, [%2];"
                 : "=r"(r[0]),"=r"(r[1]) : "r"(addr));
}
__device__ __forceinline__ void mma16816(float* c, const uint32_t* a, const uint32_t* b){
    asm volatile("mma.sync.aligned.m16n8k16.row.col.f32.bf16.bf16.f32 "
        "{%0,%1,%2,%3}, {%4,%5,%6,%7}, {%8,%9}, {%0,%1,%2,%3};"
        : "+f"(c[0]),"+f"(c[1]),"+f"(c[2]),"+f"(c[3])
        : "r"(a[0]),"r"(a[1]),"r"(a[2]),"r"(a[3]), "r"(b[0]),"r"(b[1]));
}
__device__ __forceinline__ void cp_async16(uint32_t saddr, const void* gaddr){
    asm volatile("cp.async.cg.shared.global [%0], [%1], 16;" :: "r"(saddr), "l"(gaddr));
}
#define CP_COMMIT() asm volatile("cp.async.commit_group;" ::: "memory")
#define CP_WAIT0()  asm volatile("cp.async.wait_group 0;" ::: "memory")

// -------------------- threefry2x32 (JAX-compatible) -----------------------
__device__ __forceinline__ unsigned rotl32(unsigned v, int r){ return (v<<r)|(v>>(32-r)); }

__device__ void threefry2x32(unsigned k0, unsigned k1, unsigned x0, unsigned x1,
                             unsigned &o0, unsigned &o1)
{
    unsigned ks0=k0, ks1=k1, ks2 = k0 ^ k1 ^ 0x1BD11BDAu;
    x0 += ks0; x1 += ks1;
#define TF_RND(r) { x0 += x1; x1 = rotl32(x1, r); x1 ^= x0; }
    TF_RND(13) TF_RND(15) TF_RND(26) TF_RND(6)
    x0 += ks1; x1 += ks2 + 1u;
    TF_RND(17) TF_RND(29) TF_RND(16) TF_RND(24)
    x0 += ks2; x1 += ks0 + 2u;
    TF_RND(13) TF_RND(15) TF_RND(26) TF_RND(6)
    x0 += ks0; x1 += ks1 + 3u;
    TF_RND(17) TF_RND(29) TF_RND(16) TF_RND(24)
    x0 += ks1; x1 += ks2 + 4u;
    TF_RND(13) TF_RND(15) TF_RND(26) TF_RND(6)
    x0 += ks2; x1 += ks0 + 5u;
#undef TF_RND
    o0 = x0; o1 = x1;
}

__device__ float erfinv_f(float x)
{
    float w = -log1pf(-x*x);
    float p;
    if (w < 5.0f) {
        w = w - 2.5f;
        p =               2.81022636e-08f;
        p = fmaf(p, w,    3.43273939e-07f);
        p = fmaf(p, w,   -3.5233877e-06f);
        p = fmaf(p, w,   -4.39150654e-06f);
        p = fmaf(p, w,    0.00021858087f);
        p = fmaf(p, w,   -0.00125372503f);
        p = fmaf(p, w,   -0.00417768164f);
        p = fmaf(p, w,    0.246640727f);
        p = fmaf(p, w,    1.50140941f);
    } else {
        w = sqrtf(w) - 3.0f;
        p =              -0.000200214257f;
        p = fmaf(p, w,    0.000100950558f);
        p = fmaf(p, w,    0.00134934322f);
        p = fmaf(p, w,   -0.00367342844f);
        p = fmaf(p, w,    0.00573950773f);
        p = fmaf(p, w,   -0.0076224613f);
        p = fmaf(p, w,    0.00943887047f);
        p = fmaf(p, w,    1.00167406f);
        p = fmaf(p, w,    2.83297682f);
    }
    return p * x;
}

__device__ float jax_normal_elem(unsigned i)
{
    unsigned y0, y1;
    threefry2x32(0u, 42u, 0u, i, y0, y1);
    unsigned bits = y0 ^ y1;
    float f  = __uint_as_float((bits >> 9) | 0x3f800000u) - 1.0f;
    const float lo = -0.99999994f;
    float u = fmaxf(lo, fmaf(f, 2.0f, lo));
    return 1.41421356f * erfinv_f(u);
}

// -------------------- small kernels ---------------------------------------
__global__ void embed_k(const int* __restrict__ idx, const float* __restrict__ tok,
                        const float* __restrict__ pos, float* __restrict__ x,
                        int* __restrict__ cnt)
{
    int gid = blockIdx.x * blockDim.x + threadIdx.x;
    if (gid < NE) cnt[gid] = 0;          // layer-0 router cnt reset (fused)
    int r = gid >> 7, c = gid & 127;
    int t = r & (TT - 1);
    x[gid] = tok[idx[r] * CC + c] + pos[t * CC + c];
}

__global__ void layernorm_k(const float* __restrict__ x, const float* __restrict__ g,
                            const float* __restrict__ b, float* __restrict__ out)
{
    int row = blockIdx.x, c = threadIdx.x;
    __shared__ float red[CC];
    float v = x[row * CC + c];
    red[c] = v; __syncthreads();
    for (int s = 64; s > 0; s >>= 1) { if (c < s) red[c] += red[c + s]; __syncthreads(); }
    float mean = red[0] * (1.0f / CC);
    __syncthreads();
    float d = v - mean;
    red[c] = d * d; __syncthreads();
    for (int s = 64; s > 0; s >>= 1) { if (c < s) red[c] += red[c + s]; __syncthreads(); }
    float var = red[0] * (1.0f / CC);
    out[row * CC + c] = d / sqrtf(var + 1e-5f) * g[c] + b[c];
}

__global__ void pack_qkv_all_k(const float* __restrict__ Wq, const float* __restrict__ Wk,
                               const float* __restrict__ Wv, float* __restrict__ wp)
{
    int gid = blockIdx.x * blockDim.x + threadIdx.x;   // NL*CC*384
    int l   = gid / (CC * 384);
    int rem = gid % (CC * 384);
    int c = rem / 384, j = rem % 384;
    size_t lw = (size_t)l * NH * CC * HS;
    const float* W = (j < 128) ? (Wq + lw) : (j < 256 ? (Wk + lw) : (Wv + lw));
    int jj = j & 127;
    int hh = jj >> 5, dd = jj & 31;
    wp[gid] = W[(hh * CC + c) * HS + dd];
}

// pack Wlm -> transposed bf16 hi/lo: bpack[n][k] = bf16split(Wlm[k][n])
__global__ void pack_b_k(const float* __restrict__ Wlm,
                         __nv_bfloat16* __restrict__ bh, __nv_bfloat16* __restrict__ bl)
{
    __shared__ float s[32][33];
    int n0 = blockIdx.x * 32, k0 = blockIdx.y * 32;
    int tx = threadIdx.x, ty = threadIdx.y;
    int n = n0 + tx;
    s[ty][tx] = (n < VV) ? Wlm[(size_t)(k0 + ty) * VV + n] : 0.f;
    __syncthreads();
    float f = s[tx][ty];
    __nv_bfloat16 hi = __float2bfloat16(f);
    float lo = f - __bfloat162float(hi);
    size_t o = (size_t)(n0 + ty) * CC + k0 + tx;
    bh[o] = hi;
    bl[o] = __float2bfloat16(lo);
}

__global__ void pack_a_k(const float* __restrict__ h,
                         __nv_bfloat16* __restrict__ ah, __nv_bfloat16* __restrict__ al)
{
    int i = blockIdx.x * blockDim.x + threadIdx.x;
    float f = h[i];
    __nv_bfloat16 hi = __float2bfloat16(f);
    ah[i] = hi;
    al[i] = __float2bfloat16(f - __bfloat162float(hi));
}

__global__ void attention_k(const float* __restrict__ qkv, float* __restrict__ att)
{
    int b = blockIdx.x >> 2, h = blockIdx.x & 3;
    int t = threadIdx.y, s = threadIdx.x;
    __shared__ float qs[TT][HS+1], ks[TT][HS+1], vs[TT][HS+1], ws[TT][TT+1];
    int base = (b * TT + t) * (3 * CC) + h * HS;
    qs[t][s] = qkv[base + s];
    ks[t][s] = qkv[base + CC + s];
    vs[t][s] = qkv[base + 2 * CC + s];
    __syncthreads();
    const float NEG_INF = __int_as_float(0xff800000);
    float w;
    if (s <= t) {
        float acc = 0.f;
#pragma unroll
        for (int d = 0; d < HS; d++) acc = fmaf(qs[t][d], ks[s][d], acc);
        w = acc * 0.08838834764831845f;
    } else w = NEG_INF;
    float m = w;
#pragma unroll
    for (int o = 16; o; o >>= 1) m = fmaxf(m, __shfl_xor_sync(0xffffffffu, m, o));
    float e = (s <= t) ? expf(w - m) : 0.f;
    float sum = e;
#pragma unroll
    for (int o = 16; o; o >>= 1) sum += __shfl_xor_sync(0xffffffffu, sum, o);
    ws[t][s] = e / sum;
    __syncthreads();
    float acc = 0.f;
#pragma unroll
    for (int k = 0; k < TT; k++) acc = fmaf(ws[t][k], vs[k][s], acc);
    att[(b * TT + t) * CC + h * HS + s] = acc;
}

__global__ void router_ln_k(const float* __restrict__ x,
                            const float* __restrict__ g2, const float* __restrict__ b2,
                            const float* __restrict__ Wr, const float* __restrict__ br,
                            const float* __restrict__ Wn, const float* __restrict__ bn,
                            const float* __restrict__ Ws, const float* __restrict__ bs,
                            float* __restrict__ nx, float* __restrict__ gates,
                            int* __restrict__ cnt, int* __restrict__ list,
                            int4* __restrict__ slot, int layer)
{
    int row = blockIdx.x, c = threadIdx.x;
    __shared__ float red[9][CC];
    float xv = x[row * CC + c];
    red[0][c] = xv; __syncthreads();
    for (int s = 64; s > 0; s >>= 1) { if (c < s) red[0][c] += red[0][c + s]; __syncthreads(); }
    float mean = red[0][0] * (1.0f / CC);
    __syncthreads();
    float d = xv - mean;
    red[0][c] = d * d; __syncthreads();
    for (int s = 64; s > 0; s >>= 1) { if (c < s) red[0][c] += red[0][c + s]; __syncthreads(); }
    float var = red[0][0] * (1.0f / CC);
    __syncthreads();
    float v = d / sqrtf(var + 1e-5f) * g2[c] + b2[c];
    nx[row * CC + c] = v;
#pragma unroll
    for (int e = 0; e < NE; e++) {
        red[e][c]     = v * Wr[c * NE + e];
        red[4 + e][c] = v * Wn[c * NE + e];
    }
    red[8][c] = v * Ws[c];
    __syncthreads();
    for (int st = 64; st > 0; st >>= 1) {
        if (c < st) {
#pragma unroll
            for (int j = 0; j < 9; j++) red[j][c] += red[j][c + st];
        }
        __syncthreads();
    }
    if (c == 0) {
        float noisy[NE];
#pragma unroll
        for (int e = 0; e < NE; e++) {
            float logit = red[e][0] + br[e];
            float nl    = red[4 + e][0] + bn[e];
            float sp    = fmaxf(nl, 0.f) + log1pf(expf(-fabsf(nl)));
            unsigned i  = ((unsigned)(layer * NT + row)) * NE + e;
            noisy[e]    = logit + jax_normal_elem(i) * sp;
        }
        int i1 = 0;
        for (int e = 1; e < NE; e++) if (noisy[e] > noisy[i1]) i1 = e;
        int i2 = -1;
        for (int e = 0; e < NE; e++) if (e != i1 && (i2 < 0 || noisy[e] > noisy[i2])) i2 = e;
        float mx = noisy[i1];
        float gv[NE], gsum = 0.f;
#pragma unroll
        for (int e = 0; e < NE; e++) {
            gv[e] = (e == i1 || e == i2) ? expf(noisy[e] - mx) : 0.f;
            gsum += gv[e];
        }
#pragma unroll
        for (int e = 0; e < NE; e++) gates[row * NE + e] = gv[e] / gsum;
        int skipped = (red[8][0] + bs[0] > 0.f);
        if (!skipped) {
            int ea = i1 < i2 ? i1 : i2;
            int eb = i1 < i2 ? i2 : i1;
            int pa = atomicAdd(&cnt[ea], 1); list[ea * NT + pa] = row;
            int pb = atomicAdd(&cnt[eb], 1); list[eb * NT + pb] = row;
            slot[row] = make_int4(ea, pa, eb, pb);
        } else {
            slot[row] = make_int4(-1, 0, -1, 0);
        }
    }
}

// fused combine + next layernorm; also zeroes cnt for the NEXT layer's router
__global__ void combine_ln_k(float* __restrict__ x, const float* __restrict__ eoc,
                             const int4* __restrict__ slot,
                             const float* __restrict__ g, const float* __restrict__ b,
                             float* __restrict__ hout, int* __restrict__ cnt)
{
    int row = blockIdx.x, c = threadIdx.x;
    __shared__ float red[CC];
    int4 s = slot[row];
    float v = x[row * CC + c];
    if (s.x >= 0)
        v += eoc[((size_t)s.x * NT + s.y) * CC + c]
           + eoc[((size_t)s.z * NT + s.w) * CC + c];
    x[row * CC + c] = v;
    if (row == 0 && c < NE) cnt[c] = 0;      // reset for next layer's router
    red[c] = v; __syncthreads();
    for (int st = 64; st > 0; st >>= 1) { if (c < st) red[c] += red[c + st]; __syncthreads(); }
    float mean = red[0] * (1.0f / CC);
    __syncthreads();
    float d = v - mean;
    red[c] = d * d; __syncthreads();
    for (int st = 64; st > 0; st >>= 1) { if (c < st) red[c] += red[c + st]; __syncthreads(); }
    float var = red[0] * (1.0f / CC);
    hout[row * CC + c] = d / sqrtf(var + 1e-5f) * g[c] + b[c];
}

// -------------------- FFMA2 helper ----------------------------------------
__device__ __forceinline__ void ffma2(u64 &d, u64 a, u64 b)
{
    asm("fma.rn.f32x2 %0, %1, %2, %0;" : "+l"(d) : "l"(a), "l"(b));
}

enum { EPI_BIAS = 0, EPI_RELU = 1, EPI_RESID = 2, EPI_GATE_WR = 3 };

// -------------------- 64x64 SGEMM (proj only) ------------------------------
#define BM 64
#define BN 64
#define BK 16

template<int EPI>
__global__ void __launch_bounds__(256, 4)
sgemm_k(const float* __restrict__ A, const float* __restrict__ B,
        const float* __restrict__ bias, float* __restrict__ C,
        int M, int N, int K)
{
    __shared__ float2 As2[BK][BM];
    __shared__ float  Bs [BK][BN];
    int tid = threadIdx.x;
    int n0 = blockIdx.x * BN, m0 = blockIdx.y * BM;
    int tx = tid & 15, ty = tid >> 4;
    int am = tid >> 2,  ak = (tid & 3) * 4;
    int bk = tid >> 4,  bn = (tid & 15) * 4;

    u64 acc[4][2];
#pragma unroll
    for (int i = 0; i < 4; i++) { acc[i][0] = 0ull; acc[i][1] = 0ull; }

    for (int k0 = 0; k0 < K; k0 += BK) {
        float4 av = *reinterpret_cast<const float4*>(&A[(size_t)(m0 + am) * K + k0 + ak]);
        As2[ak + 0][am] = make_float2(av.x, av.x);
        As2[ak + 1][am] = make_float2(av.y, av.y);
        As2[ak + 2][am] = make_float2(av.z, av.z);
        As2[ak + 3][am] = make_float2(av.w, av.w);
        const float* Brow = &B[(size_t)(k0 + bk) * N + n0 + bn];
        Bs[bk][bn + 0] = Brow[0]; Bs[bk][bn + 1] = Brow[1];
        Bs[bk][bn + 2] = Brow[2]; Bs[bk][bn + 3] = Brow[3];
        __syncthreads();
#pragma unroll
        for (int k = 0; k < BK; k++) {
            u64 a[4];
#pragma unroll
            for (int i = 0; i < 4; i++)
                a[i] = *reinterpret_cast<const u64*>(&As2[k][ty * 4 + i]);
            ulonglong2 bv = *reinterpret_cast<const ulonglong2*>(&Bs[k][tx * 4]);
#pragma unroll
            for (int i = 0; i < 4; i++) {
                ffma2(acc[i][0], a[i], bv.x);
                ffma2(acc[i][1], a[i], bv.y);
            }
        }
        __syncthreads();
    }

#pragma unroll
    for (int i = 0; i < 4; i++) {
        int m = m0 + ty * 4 + i;
#pragma unroll
        for (int p = 0; p < 2; p++) {
            float vlo = __uint_as_float((unsigned)(acc[i][p] & 0xffffffffull));
            float vhi = __uint_as_float((unsigned)(acc[i][p] >> 32));
#pragma unroll
            for (int q = 0; q < 2; q++) {
                int n = n0 + tx * 4 + p * 2 + q;
                float val = (q == 0 ? vlo : vhi) + (bias ? bias[n] : 0.f);
                size_t o = (size_t)m * N + n;
                if      (EPI == EPI_BIAS)  C[o] = val;
                else if (EPI == EPI_RESID) C[o] = C[o] + val;
            }
        }
    }
}

// -------------------- 128x128 SGEMM (QKV / MoE compact) --------------------
#define QM 128
#define QN 128
#define QK 16

template<int EPI, int INDA>
__global__ void __launch_bounds__(256, 2)
sgemm128_k(const float* __restrict__ A, const float* __restrict__ B,
           const float* __restrict__ bias, float* __restrict__ C,
           int M, int N, int K, const float* __restrict__ gates, int gstride,
           long zsA, long zsB, long zsBias, long zsC,
           const int* __restrict__ rows_all, const int* __restrict__ cnts)
{
    const int z  = blockIdx.z;
    const int Mz = cnts ? cnts[z] : M;
    const int m0 = blockIdx.y * QM;
    if (m0 >= Mz) return;

    __shared__ __align__(16) float  As [2][QK][QM];
    __shared__ __align__(16) float2 Bs2[2][QK][QN];
    const int tid = threadIdx.x;
    const int tx = tid & 15, ty = tid >> 4;
    const int n0 = blockIdx.x * QN;
    A += (size_t)z * zsA; B += (size_t)z * zsB; C += (size_t)z * zsC;
    const float* bz = bias ? bias + (size_t)z * zsBias : nullptr;
    const int* rows = rows_all ? rows_all + (size_t)z * NT : nullptr;

    const int am = tid >> 1, ak = (tid & 1) * 8;
    const int bk = tid >> 5, bn = (tid & 31) * 4;

    size_t arow;
    {
        int r = m0 + am;
        if (INDA) {
            int rr = (r < Mz) ? r : (Mz - 1);
            arow = (size_t)rows[rr];
        } else {
            arow = (size_t)r;
        }
    }
    const float* Abase = A + arow * (size_t)K;

    u64 acc[4][8];
#pragma unroll
    for (int i = 0; i < 4; i++)
#pragma unroll
        for (int j = 0; j < 8; j++) acc[i][j] = 0ull;

    float4 pa0, pa1;
    float  pb[2][4];
    {
        pa0 = *reinterpret_cast<const float4*>(Abase + ak);
        pa1 = *reinterpret_cast<const float4*>(Abase + ak + 4);
#pragma unroll
        for (int r = 0; r < 2; r++) {
            int kk = bk + r * 8;
#pragma unroll
            for (int j = 0; j < 4; j++) {
                int n = n0 + bn + j;
                pb[r][j] = (n < N) ? B[(size_t)kk * N + n] : 0.f;
            }
        }
    }

    const int ktiles = K >> 4;
    for (int kt = 0; kt < ktiles; kt++) {
        const int sb = kt & 1;
        As[sb][ak + 0][am] = pa0.x; As[sb][ak + 1][am] = pa0.y;
        As[sb][ak + 2][am] = pa0.z; As[sb][ak + 3][am] = pa0.w;
        As[sb][ak + 4][am] = pa1.x; As[sb][ak + 5][am] = pa1.y;
        As[sb][ak + 6][am] = pa1.z; As[sb][ak + 7][am] = pa1.w;
#pragma unroll
        for (int r = 0; r < 2; r++)
#pragma unroll
            for (int j = 0; j < 4; j++)
                Bs2[sb][bk + r * 8][bn + j] = make_float2(pb[r][j], pb[r][j]);
        __syncthreads();

        if (kt + 1 < ktiles) {
            int k0 = (kt + 1) * QK;
            pa0 = *reinterpret_cast<const float4*>(Abase + k0 + ak);
            pa1 = *reinterpret_cast<const float4*>(Abase + k0 + ak + 4);
#pragma unroll
            for (int r = 0; r < 2; r++) {
                int kk = k0 + bk + r * 8;
#pragma unroll
                for (int j = 0; j < 4; j++) {
                    int n = n0 + bn + j;
                    pb[r][j] = (n < N) ? B[(size_t)kk * N + n] : 0.f;
                }
            }
        }

#pragma unroll
        for (int k = 0; k < QK; k++) {
            u64 a[4];
#pragma unroll
            for (int i = 0; i < 4; i++)
                a[i] = *reinterpret_cast<const u64*>(&As[sb][k][ty * 8 + 2 * i]);
            u64 b[8];
#pragma unroll
            for (int j4 = 0; j4 < 4; j4++) {
                ulonglong2 v = *reinterpret_cast<const ulonglong2*>(&Bs2[sb][k][tx * 2 + 32 * j4]);
                b[2 * j4] = v.x; b[2 * j4 + 1] = v.y;
            }
#pragma unroll
            for (int i = 0; i < 4; i++)
#pragma unroll
                for (int j = 0; j < 8; j++)
                    ffma2(acc[i][j], a[i], b[j]);
        }
    }

    float bv[8];
#pragma unroll
    for (int j4 = 0; j4 < 4; j4++) {
        int n = n0 + tx * 2 + 32 * j4;
        bv[2 * j4]     = (bz && n     < N) ? bz[n]     : 0.f;
        bv[2 * j4 + 1] = (bz && n + 1 < N) ? bz[n + 1] : 0.f;
    }

#pragma unroll
    for (int mp = 0; mp < 4; mp++) {
#pragma unroll
        for (int hh = 0; hh < 2; hh++) {
            int m = m0 + ty * 8 + mp * 2 + hh;
            if (m >= Mz) continue;
            float gate = 1.f;
            if (EPI == EPI_GATE_WR) {
                int tok = rows ? rows[m] : m;
                gate = gates[(size_t)tok * gstride + z];
            }
            size_t rowb = (size_t)m * N;
#pragma unroll
            for (int j4 = 0; j4 < 4; j4++) {
                int n = n0 + tx * 2 + 32 * j4;
                u64 t0 = acc[mp][2 * j4], t1 = acc[mp][2 * j4 + 1];
                float v0 = hh ? __uint_as_float((unsigned)(t0 >> 32))
                              : __uint_as_float((unsigned)(t0 & 0xffffffffull));
                float v1 = hh ? __uint_as_float((unsigned)(t1 >> 32))
                              : __uint_as_float((unsigned)(t1 & 0xffffffffull));
                v0 += bv[2 * j4]; v1 += bv[2 * j4 + 1];
                if (EPI == EPI_RELU)    { v0 = fmaxf(v0, 0.f); v1 = fmaxf(v1, 0.f); }
                if (EPI == EPI_GATE_WR) { v0 *= gate; v1 *= gate; }
                size_t o = rowb + n;
                if (n + 1 < N && (o & 1) == 0) {
                    *reinterpret_cast<float2*>(&C[o]) = make_float2(v0, v1);
                } else {
                    if (n < N)     C[o]     = v0;
                    if (n + 1 < N) C[o + 1] = v1;
                }
            }
        }
    }
}

// -------------------- mma.sync bf16x3 LM head ------------------------------
// D[4096, VV] = Ah*Bh^T + Al*Bh^T + Ah*Bl^T, fp32 accum in registers.
// CTA: A tile 128m x K=128 resident in smem (hi+lo); LM_NTILES n-tiles of 64.
// Mainloop = R13 form (no long-lived prefetch registers). Next tile's B is
// prefetched with cp.async (zero register cost) after the post-mainloop sync,
// overlapping the epilogue's STG work; wait_group before the next mainloop.
__global__ void __launch_bounds__(256, 2)
lmhead_mma_k(const __nv_bfloat16* __restrict__ ah, const __nv_bfloat16* __restrict__ al,
             const __nv_bfloat16* __restrict__ bh, const __nv_bfloat16* __restrict__ bl,
             const float* __restrict__ bias, float* __restrict__ out)
{
    extern __shared__ __align__(16) __nv_bfloat16 sm[];
    __nv_bfloat16* sAh = sm;
    __nv_bfloat16* sAl = sm + 128 * LMS;
    __nv_bfloat16* sBh = sm + 2 * 128 * LMS;
    __nv_bfloat16* sBl = sBh + 64 * LMS;
    const int tid = threadIdx.x;
    const int m0 = blockIdx.x * 128;
    const int nbase = blockIdx.y * LM_NTILES * 64;

    const int brow = tid >> 4, bcol = (tid & 15) * 8;   // B staging coords
    const uint32_t sBh_u = smem_u32(sBh), sBl_u = smem_u32(sBl);

    // B(0) via cp.async (overlaps A's LDG+STS below), A direct
#pragma unroll
    for (int i = 0; i < 4; i++) {
        int row = brow + i * 16;
        cp_async16(sBh_u + (uint32_t)(row * LMS + bcol) * 2,
                   bh + (size_t)(nbase + row) * CC + bcol);
        cp_async16(sBl_u + (uint32_t)(row * LMS + bcol) * 2,
                   bl + (size_t)(nbase + row) * CC + bcol);
    }
    CP_COMMIT();
#pragma unroll
    for (int i = 0; i < 8; i++) {
        int idx = tid + i * 256; int row = idx >> 4, c = (idx & 15) * 8;
        *reinterpret_cast<uint4*>(sAh + row * LMS + c) =
            *reinterpret_cast<const uint4*>(ah + (size_t)(m0 + row) * CC + c);
        *reinterpret_cast<uint4*>(sAl + row * LMS + c) =
            *reinterpret_cast<const uint4*>(al + (size_t)(m0 + row) * CC + c);
    }
    CP_WAIT0();
    __syncthreads();

    const int w = tid >> 5, lane = tid & 31;
    const int wm = w >> 1, wn = w & 1;

    const __nv_bfloat16* Ap[3] = { sAh, sAl, sAh };
    const __nv_bfloat16* Bp[3] = { sBh, sBh, sBl };

    for (int nt = 0; nt < LM_NTILES; nt++) {
        const int n0 = nbase + nt * 64;

        float acc[2][4][4];
#pragma unroll
        for (int mt = 0; mt < 2; mt++)
#pragma unroll
            for (int ntl = 0; ntl < 4; ntl++)
#pragma unroll
                for (int q = 0; q < 4; q++) acc[mt][ntl][q] = 0.f;

#pragma unroll
        for (int pass = 0; pass < 3; pass++) {
            const uint32_t abase = smem_u32(Ap[pass]);
            const uint32_t bbase = smem_u32(Bp[pass]);
#pragma unroll
            for (int ks = 0; ks < 8; ks++) {
                const int k0 = ks * 16;
                uint32_t af[2][4];
#pragma unroll
                for (int mt = 0; mt < 2; mt++) {
                    int row = wm * 32 + mt * 16 + (lane & 15);
                    ldmatrix_x4(af[mt], abase + (uint32_t)(row * LMS + k0 + (lane >> 4) * 8) * 2);
                }
                uint32_t bf[4][2];
#pragma unroll
                for (int ntl = 0; ntl < 4; ntl++) {
                    int nr = wn * 32 + ntl * 8 + (lane & 7);
                    ldmatrix_x2(bf[ntl], bbase + (uint32_t)(nr * LMS + k0 + ((lane >> 3) & 1) * 8) * 2);
                }
#pragma unroll
                for (int mt = 0; mt < 2; mt++)
#pragma unroll
                    for (int ntl = 0; ntl < 4; ntl++)
                        mma16816(acc[mt][ntl], af[mt], bf[ntl]);
            }
        }

        __syncthreads();   // all warps done reading B(nt)

        // cp.async prefetch of B(nt+1): zero registers, overlaps epilogue STGs
        if (nt + 1 < LM_NTILES) {
#pragma unroll
            for (int i = 0; i < 4; i++) {
                int row = brow + i * 16;
                cp_async16(sBh_u + (uint32_t)(row * LMS + bcol) * 2,
                           bh + (size_t)(n0 + 64 + row) * CC + bcol);
                cp_async16(sBl_u + (uint32_t)(row * LMS + bcol) * 2,
                           bl + (size_t)(n0 + 64 + row) * CC + bcol);
            }
            CP_COMMIT();
        }

        // epilogue: D frag c0,c1 -> (m = lane>>2, n = (lane&3)*2+{0,1}); c2,c3 -> m+8
#pragma unroll
        for (int ntl = 0; ntl < 4; ntl++) {
            int n = n0 + wn * 32 + ntl * 8 + (lane & 3) * 2;
            float b0 = (n     < VV) ? bias[n]     : 0.f;
            float b1 = (n + 1 < VV) ? bias[n + 1] : 0.f;
#pragma unroll
            for (int mt = 0; mt < 2; mt++) {
#pragma unroll
                for (int half = 0; half < 2; half++) {
                    int m = m0 + wm * 32 + mt * 16 + (lane >> 2) + half * 8;
                    float v0 = acc[mt][ntl][half * 2 + 0] + b0;
                    float v1 = acc[mt][ntl][half * 2 + 1] + b1;
                    size_t o = (size_t)m * VV + n;
                    if (n + 1 < VV && (o & 1) == 0) {
                        *reinterpret_cast<float2*>(out + o) = make_float2(v0, v1);
                    } else {
                        if (n     < VV) out[o]     = v0;
                        if (n + 1 < VV) out[o + 1] = v1;
                    }
                }
            }
        }
        if (nt + 1 < LM_NTILES) CP_WAIT0();
        __syncthreads();   // B(nt+1) visible before next mainloop
    }
}

// -------------------- host orchestration ----------------------------------
extern "C" void kernel_launch(void* const* d_in, const int* in_sizes, int n_in,
                              void* d_out, int out_size)
{
    (void)in_sizes; (void)n_in; (void)out_size;
    const int*   idx  = (const int*)  d_in[0];
    const float* tok  = (const float*)d_in[1];
    const float* pos  = (const float*)d_in[2];
    const float* ln1g = (const float*)d_in[3];
    const float* ln1b = (const float*)d_in[4];
    const float* Wq   = (const float*)d_in[5];
    const float* Wk   = (const float*)d_in[6];
    const float* Wv   = (const float*)d_in[7];
    const float* Wo   = (const float*)d_in[8];
    const float* bo   = (const float*)d_in[9];
    const float* ln2g = (const float*)d_in[10];
    const float* ln2b = (const float*)d_in[11];
    const float* Wr   = (const float*)d_in[12];
    const float* br   = (const float*)d_in[13];
    const float* Wn   = (const float*)d_in[14];
    const float* bn   = (const float*)d_in[15];
    const float* Wsr  = (const float*)d_in[16];
    const float* bsr  = (const float*)d_in[17];
    const float* W1   = (const float*)d_in[18];
    const float* b1   = (const float*)d_in[19];
    const float* W2   = (const float*)d_in[20];
    const float* b2   = (const float*)d_in[21];
    const float* lnfg = (const float*)d_in[22];
    const float* lnfb = (const float*)d_in[23];
    const float* Wlm  = (const float*)d_in[24];
    const float* blm  = (const float*)d_in[25];
    float* out = (float*)d_out;

    float *x, *h, *qkv, *att, *nx, *h1c, *eoc, *gates, *wp;
    int *cnt, *list; int4* slot;
    __nv_bfloat16 *bhp, *blp, *ahp, *alp;
    cudaGetSymbolAddress((void**)&x,     g_x);
    cudaGetSymbolAddress((void**)&h,     g_h);
    cudaGetSymbolAddress((void**)&qkv,   g_qkv);
    cudaGetSymbolAddress((void**)&att,   g_att);
    cudaGetSymbolAddress((void**)&nx,    g_nx);
    cudaGetSymbolAddress((void**)&h1c,   g_h1c);
    cudaGetSymbolAddress((void**)&eoc,   g_eoc);
    cudaGetSymbolAddress((void**)&gates, g_gates);
    cudaGetSymbolAddress((void**)&cnt,   g_cnt);
    cudaGetSymbolAddress((void**)&list,  g_list);
    cudaGetSymbolAddress((void**)&slot,  g_slot);
    cudaGetSymbolAddress((void**)&wp,    g_wpack);
    cudaGetSymbolAddress((void**)&bhp,   g_bh);
    cudaGetSymbolAddress((void**)&blp,   g_bl);
    cudaGetSymbolAddress((void**)&ahp,   g_ah);
    cudaGetSymbolAddress((void**)&alp,   g_al);

    embed_k<<<NT * CC / 256, 256>>>(idx, tok, pos, x, cnt);
    pack_qkv_all_k<<<NL * CC * 384 / 256, 256>>>(Wq, Wk, Wv, wp);
    pack_b_k<<<dim3(LM_NPAD / 32, CC / 32), dim3(32, 32)>>>(Wlm, bhp, blp);
    layernorm_k<<<NT, CC>>>(x, ln1g, ln1b, h);

    for (int l = 0; l < NL; l++) {
        sgemm128_k<EPI_BIAS, 0><<<dim3(384 / QN, NT / QM), 256>>>(
            h, wp + (size_t)l * CC * 384, nullptr, qkv, NT, 384, CC, nullptr, 0,
            0, 0, 0, 0, nullptr, nullptr);
        attention_k<<<NT / TT * NH, dim3(32, 32)>>>(qkv, att);
        sgemm_k<EPI_RESID><<<dim3(CC / BN, NT / BM), 256>>>(att, Wo + l * CC * CC,
                                                            bo + l * CC, x, NT, CC, CC);
        router_ln_k<<<NT, CC>>>(x, ln2g + l * CC, ln2b + l * CC,
                                Wr + l * CC * NE, br + l * NE,
                                Wn + l * CC * NE, bn + l * NE,
                                Wsr + l * CC, bsr + l,
                                nx, gates, cnt, list, slot, l);
        sgemm128_k<EPI_RELU, 1><<<dim3(FF / QN, NT / QM, NE), 256>>>(
            nx, W1 + (size_t)l * NE * CC * FF, b1 + (size_t)l * NE * FF, h1c,
            NT, FF, CC, nullptr, 0,
            0, (long)CC * FF, FF, (long)NT * FF, list, cnt);
        sgemm128_k<EPI_GATE_WR, 0><<<dim3(CC / QN, NT / QM, NE), 256>>>(
            h1c, W2 + (size_t)l * NE * FF * CC, b2 + (size_t)l * NE * CC, eoc,
            NT, CC, FF, gates, NE,
            (long)NT * FF, (long)FF * CC, CC, (long)NT * CC, list, cnt);
        const float* gnext = (l + 1 < NL) ? (ln1g + (l + 1) * CC) : lnfg;
        const float* bnext = (l + 1 < NL) ? (ln1b + (l + 1) * CC) : lnfb;
        combine_ln_k<<<NT, CC>>>(x, eoc, slot, gnext, bnext, h, cnt);
    }

    pack_a_k<<<NT * CC / 256, 256>>>(h, ahp, alp);
    cudaFuncSetAttribute(lmhead_mma_k, cudaFuncAttributeMaxDynamicSharedMemorySize, LM_SMEM);
    lmhead_mma_k<<<dim3(NT / 128, LM_NPAD / (64 * LM_NTILES)), 256, LM_SMEM>>>(
        ahp, alp, bhp, blp, blm, out);
}

// round 17
// speedup vs baseline: 1.0958x; 1.0088x over previous
#include <cuda_runtime.h>
#include <cuda_bf16.h>
#include <math.h>
#include <stdint.h>

typedef unsigned long long u64;

#define NT   4096   // B*T
#define CC   128    // n_embed
#define TT   32     // block_size
#define NH   4      // heads
#define HS   32     // head size
#define NE   4      // experts
#define NL   4      // layers
#define VV   50257  // vocab
#define FF   512    // 4*C

#define LM_NPAD 50688                 // >= VV, multiple of 512
#define LMS     136                   // padded k-stride (272B = 17*16B)
#define LM_SMEM (2*128*LMS*2 + 2*64*LMS*2)   // 104448 bytes
#define LM_NTILES 8                   // n-tiles per CTA (A reuse)

#define AP_SMEM ((TT*385 + TT*33 + TT*129) * 4)   // attn_proj dyn smem: 70016 B

// -------------------- scratch (device globals; no allocs allowed) ---------
__device__ float g_x   [NT*CC];
__device__ float g_h   [NT*CC];
__device__ float g_qkv [NT*3*CC];
__device__ float g_nx  [NT*CC];
__device__ float g_h1c [(size_t)NE*NT*FF];
__device__ float g_eoc [(size_t)NE*NT*CC];
__device__ float g_gates[NT*NE];
__device__ int   g_cnt [NE];
__device__ int   g_list[NE*NT];
__device__ int4  g_slot[NT];
__device__ float g_wpack[(size_t)NL*CC*3*CC];
__device__ __nv_bfloat16 g_bh[(size_t)LM_NPAD*CC];   // Wlm^T hi  [n][k]
__device__ __nv_bfloat16 g_bl[(size_t)LM_NPAD*CC];   // Wlm^T lo
__device__ __nv_bfloat16 g_ah[(size_t)NT*CC];        // h hi
__device__ __nv_bfloat16 g_al[(size_t)NT*CC];        // h lo

// -------------------- baseline-PTX mma / cp.async helpers ------------------
__device__ __forceinline__ uint32_t smem_u32(const void* p){
    uint32_t a;
    asm("{ .reg .u64 t; cvta.to.shared.u64 t, %1; cvt.u32.u64 %0, t; }" : "=r"(a) : "l"(p));
    return a;
}
__device__ __forceinline__ void ldmatrix_x4(uint32_t* r, uint32_t addr){
    asm volatile("ldmatrix.sync.aligned.m8n8.x4.shared.b16 {%0,%1,%2,%3}, [%4];"
                 : "=r"(r[0]),"=r"(r[1]),"=r"(r[2]),"=r"(r[3]) : "r"(addr));
}
__device__ __forceinline__ void ldmatrix_x2(uint32_t* r, uint32_t addr){
    asm volatile("ldmatrix.sync.aligned.m8n8.x2.shared.b16 {%0,%1}, [%2];"
                 : "=r"(r[0]),"=r"(r[1]) : "r"(addr));
}
__device__ __forceinline__ void mma16816(float* c, const uint32_t* a, const uint32_t* b){
    asm volatile("mma.sync.aligned.m16n8k16.row.col.f32.bf16.bf16.f32 "
        "{%0,%1,%2,%3}, {%4,%5,%6,%7}, {%8,%9}, {%0,%1,%2,%3};"
        : "+f"(c[0]),"+f"(c[1]),"+f"(c[2]),"+f"(c[3])
        : "r"(a[0]),"r"(a[1]),"r"(a[2]),"r"(a[3]), "r"(b[0]),"r"(b[1]));
}
__device__ __forceinline__ void cp_async16(uint32_t saddr, const void* gaddr){
    asm volatile("cp.async.cg.shared.global [%0], [%1], 16;" :: "r"(saddr), "l"(gaddr));
}
#define CP_COMMIT() asm volatile("cp.async.commit_group;" ::: "memory")
#define CP_WAIT0()  asm volatile("cp.async.wait_group 0;" ::: "memory")

// -------------------- threefry2x32 (JAX-compatible) -----------------------
__device__ __forceinline__ unsigned rotl32(unsigned v, int r){ return (v<<r)|(v>>(32-r)); }

__device__ void threefry2x32(unsigned k0, unsigned k1, unsigned x0, unsigned x1,
                             unsigned &o0, unsigned &o1)
{
    unsigned ks0=k0, ks1=k1, ks2 = k0 ^ k1 ^ 0x1BD11BDAu;
    x0 += ks0; x1 += ks1;
#define TF_RND(r) { x0 += x1; x1 = rotl32(x1, r); x1 ^= x0; }
    TF_RND(13) TF_RND(15) TF_RND(26) TF_RND(6)
    x0 += ks1; x1 += ks2 + 1u;
    TF_RND(17) TF_RND(29) TF_RND(16) TF_RND(24)
    x0 += ks2; x1 += ks0 + 2u;
    TF_RND(13) TF_RND(15) TF_RND(26) TF_RND(6)
    x0 += ks0; x1 += ks1 + 3u;
    TF_RND(17) TF_RND(29) TF_RND(16) TF_RND(24)
    x0 += ks1; x1 += ks2 + 4u;
    TF_RND(13) TF_RND(15) TF_RND(26) TF_RND(6)
    x0 += ks2; x1 += ks0 + 5u;
#undef TF_RND
    o0 = x0; o1 = x1;
}

__device__ float erfinv_f(float x)
{
    float w = -log1pf(-x*x);
    float p;
    if (w < 5.0f) {
        w = w - 2.5f;
        p =               2.81022636e-08f;
        p = fmaf(p, w,    3.43273939e-07f);
        p = fmaf(p, w,   -3.5233877e-06f);
        p = fmaf(p, w,   -4.39150654e-06f);
        p = fmaf(p, w,    0.00021858087f);
        p = fmaf(p, w,   -0.00125372503f);
        p = fmaf(p, w,   -0.00417768164f);
        p = fmaf(p, w,    0.246640727f);
        p = fmaf(p, w,    1.50140941f);
    } else {
        w = sqrtf(w) - 3.0f;
        p =              -0.000200214257f;
        p = fmaf(p, w,    0.000100950558f);
        p = fmaf(p, w,    0.00134934322f);
        p = fmaf(p, w,   -0.00367342844f);
        p = fmaf(p, w,    0.00573950773f);
        p = fmaf(p, w,   -0.0076224613f);
        p = fmaf(p, w,    0.00943887047f);
        p = fmaf(p, w,    1.00167406f);
        p = fmaf(p, w,    2.83297682f);
    }
    return p * x;
}

__device__ float jax_normal_elem(unsigned i)
{
    unsigned y0, y1;
    threefry2x32(0u, 42u, 0u, i, y0, y1);
    unsigned bits = y0 ^ y1;
    float f  = __uint_as_float((bits >> 9) | 0x3f800000u) - 1.0f;
    const float lo = -0.99999994f;
    float u = fmaxf(lo, fmaf(f, 2.0f, lo));
    return 1.41421356f * erfinv_f(u);
}

// -------------------- small kernels ---------------------------------------
__global__ void embed_k(const int* __restrict__ idx, const float* __restrict__ tok,
                        const float* __restrict__ pos, float* __restrict__ x,
                        int* __restrict__ cnt)
{
    int gid = blockIdx.x * blockDim.x + threadIdx.x;
    if (gid < NE) cnt[gid] = 0;          // layer-0 router cnt reset (fused)
    int r = gid >> 7, c = gid & 127;
    int t = r & (TT - 1);
    x[gid] = tok[idx[r] * CC + c] + pos[t * CC + c];
}

__global__ void layernorm_k(const float* __restrict__ x, const float* __restrict__ g,
                            const float* __restrict__ b, float* __restrict__ out)
{
    int row = blockIdx.x, c = threadIdx.x;
    __shared__ float red[CC];
    float v = x[row * CC + c];
    red[c] = v; __syncthreads();
    for (int s = 64; s > 0; s >>= 1) { if (c < s) red[c] += red[c + s]; __syncthreads(); }
    float mean = red[0] * (1.0f / CC);
    __syncthreads();
    float d = v - mean;
    red[c] = d * d; __syncthreads();
    for (int s = 64; s > 0; s >>= 1) { if (c < s) red[c] += red[c + s]; __syncthreads(); }
    float var = red[0] * (1.0f / CC);
    out[row * CC + c] = d / sqrtf(var + 1e-5f) * g[c] + b[c];
}

__global__ void pack_qkv_all_k(const float* __restrict__ Wq, const float* __restrict__ Wk,
                               const float* __restrict__ Wv, float* __restrict__ wp)
{
    int gid = blockIdx.x * blockDim.x + threadIdx.x;   // NL*CC*384
    int l   = gid / (CC * 384);
    int rem = gid % (CC * 384);
    int c = rem / 384, j = rem % 384;
    size_t lw = (size_t)l * NH * CC * HS;
    const float* W = (j < 128) ? (Wq + lw) : (j < 256 ? (Wk + lw) : (Wv + lw));
    int jj = j & 127;
    int hh = jj >> 5, dd = jj & 31;
    wp[gid] = W[(hh * CC + c) * HS + dd];
}

// pack Wlm -> transposed bf16 hi/lo: bpack[n][k] = bf16split(Wlm[k][n])
__global__ void pack_b_k(const float* __restrict__ Wlm,
                         __nv_bfloat16* __restrict__ bh, __nv_bfloat16* __restrict__ bl)
{
    __shared__ float s[32][33];
    int n0 = blockIdx.x * 32, k0 = blockIdx.y * 32;
    int tx = threadIdx.x, ty = threadIdx.y;
    int n = n0 + tx;
    s[ty][tx] = (n < VV) ? Wlm[(size_t)(k0 + ty) * VV + n] : 0.f;
    __syncthreads();
    float f = s[tx][ty];
    __nv_bfloat16 hi = __float2bfloat16(f);
    float lo = f - __bfloat162float(hi);
    size_t o = (size_t)(n0 + ty) * CC + k0 + tx;
    bh[o] = hi;
    bl[o] = __float2bfloat16(lo);
}

// fused attention (4 heads) + output projection + residual, one CTA per batch
__global__ void __launch_bounds__(1024, 1)
attn_proj_k(const float* __restrict__ qkv, const float* __restrict__ Wo,
            const float* __restrict__ bo, float* __restrict__ x)
{
    extern __shared__ float dyn[];
    float* qkvs = dyn;                     // [TT][385]
    float* wssm = dyn + TT * 385;          // [TT][33]
    float* atts = wssm + TT * 33;          // [TT][129]
    const int b = blockIdx.x;
    const int tid = threadIdx.x;
    const int t = tid >> 5, s = tid & 31;  // warp = row, lane = col

    // load qkv block for this batch: 32 rows x 384 (coalesced, row per warp)
#pragma unroll
    for (int i = 0; i < 12; i++)
        qkvs[t * 385 + s + 32 * i] = qkv[(size_t)(b * TT + t) * 384 + s + 32 * i];
    __syncthreads();

    const float NEG_INF = __int_as_float(0xff800000);
#pragma unroll
    for (int h = 0; h < NH; h++) {
        float w;
        if (s <= t) {
            float acc = 0.f;
#pragma unroll
            for (int d = 0; d < HS; d++)
                acc = fmaf(qkvs[t * 385 + h * HS + d], qkvs[s * 385 + CC + h * HS + d], acc);
            w = acc * 0.08838834764831845f;            // C^-0.5 (full C=128!)
        } else w = NEG_INF;
        float m = w;
#pragma unroll
        for (int o = 16; o; o >>= 1) m = fmaxf(m, __shfl_xor_sync(0xffffffffu, m, o));
        float e = (s <= t) ? expf(w - m) : 0.f;
        float sum = e;
#pragma unroll
        for (int o = 16; o; o >>= 1) sum += __shfl_xor_sync(0xffffffffu, sum, o);
        wssm[t * 33 + s] = e / sum;
        __syncthreads();
        float acc = 0.f;
#pragma unroll
        for (int k = 0; k < TT; k++)
            acc = fmaf(wssm[t * 33 + k], qkvs[k * 385 + 2 * CC + h * HS + s], acc);
        atts[t * 129 + h * HS + s] = acc;
        __syncthreads();                   // before next head overwrites wssm
    }

    // proj + residual: x[t][4s..4s+3] += att[t][:] @ Wo[:, 4s..4s+3] + bo
    float a0 = 0.f, a1 = 0.f, a2 = 0.f, a3 = 0.f;
    const int j = 4 * s;
    for (int k = 0; k < CC; k++) {
        float av = atts[t * 129 + k];
        float4 wv = *reinterpret_cast<const float4*>(&Wo[(size_t)k * CC + j]);
        a0 = fmaf(av, wv.x, a0);
        a1 = fmaf(av, wv.y, a1);
        a2 = fmaf(av, wv.z, a2);
        a3 = fmaf(av, wv.w, a3);
    }
    size_t o = (size_t)(b * TT + t) * CC + j;
    float4 xv = *reinterpret_cast<float4*>(&x[o]);
    xv.x += a0 + bo[j + 0];
    xv.y += a1 + bo[j + 1];
    xv.z += a2 + bo[j + 2];
    xv.w += a3 + bo[j + 3];
    *reinterpret_cast<float4*>(&x[o]) = xv;
}

__global__ void router_ln_k(const float* __restrict__ x,
                            const float* __restrict__ g2, const float* __restrict__ b2,
                            const float* __restrict__ Wr, const float* __restrict__ br,
                            const float* __restrict__ Wn, const float* __restrict__ bn,
                            const float* __restrict__ Ws, const float* __restrict__ bs,
                            float* __restrict__ nx, float* __restrict__ gates,
                            int* __restrict__ cnt, int* __restrict__ list,
                            int4* __restrict__ slot, int layer)
{
    int row = blockIdx.x, c = threadIdx.x;
    __shared__ float red[9][CC];
    float xv = x[row * CC + c];
    red[0][c] = xv; __syncthreads();
    for (int s = 64; s > 0; s >>= 1) { if (c < s) red[0][c] += red[0][c + s]; __syncthreads(); }
    float mean = red[0][0] * (1.0f / CC);
    __syncthreads();
    float d = xv - mean;
    red[0][c] = d * d; __syncthreads();
    for (int s = 64; s > 0; s >>= 1) { if (c < s) red[0][c] += red[0][c + s]; __syncthreads(); }
    float var = red[0][0] * (1.0f / CC);
    __syncthreads();
    float v = d / sqrtf(var + 1e-5f) * g2[c] + b2[c];
    nx[row * CC + c] = v;
#pragma unroll
    for (int e = 0; e < NE; e++) {
        red[e][c]     = v * Wr[c * NE + e];
        red[4 + e][c] = v * Wn[c * NE + e];
    }
    red[8][c] = v * Ws[c];
    __syncthreads();
    for (int st = 64; st > 0; st >>= 1) {
        if (c < st) {
#pragma unroll
            for (int j = 0; j < 9; j++) red[j][c] += red[j][c + st];
        }
        __syncthreads();
    }
    if (c == 0) {
        float noisy[NE];
#pragma unroll
        for (int e = 0; e < NE; e++) {
            float logit = red[e][0] + br[e];
            float nl    = red[4 + e][0] + bn[e];
            float sp    = fmaxf(nl, 0.f) + log1pf(expf(-fabsf(nl)));
            unsigned i  = ((unsigned)(layer * NT + row)) * NE + e;
            noisy[e]    = logit + jax_normal_elem(i) * sp;
        }
        int i1 = 0;
        for (int e = 1; e < NE; e++) if (noisy[e] > noisy[i1]) i1 = e;
        int i2 = -1;
        for (int e = 0; e < NE; e++) if (e != i1 && (i2 < 0 || noisy[e] > noisy[i2])) i2 = e;
        float mx = noisy[i1];
        float gv[NE], gsum = 0.f;
#pragma unroll
        for (int e = 0; e < NE; e++) {
            gv[e] = (e == i1 || e == i2) ? expf(noisy[e] - mx) : 0.f;
            gsum += gv[e];
        }
#pragma unroll
        for (int e = 0; e < NE; e++) gates[row * NE + e] = gv[e] / gsum;
        int skipped = (red[8][0] + bs[0] > 0.f);
        if (!skipped) {
            int ea = i1 < i2 ? i1 : i2;
            int eb = i1 < i2 ? i2 : i1;
            int pa = atomicAdd(&cnt[ea], 1); list[ea * NT + pa] = row;
            int pb = atomicAdd(&cnt[eb], 1); list[eb * NT + pb] = row;
            slot[row] = make_int4(ea, pa, eb, pb);
        } else {
            slot[row] = make_int4(-1, 0, -1, 0);
        }
    }
}

// fused combine + next layernorm; zeroes cnt; optional bf16 hi/lo emit of h
__global__ void combine_ln_k(float* __restrict__ x, const float* __restrict__ eoc,
                             const int4* __restrict__ slot,
                             const float* __restrict__ g, const float* __restrict__ b,
                             float* __restrict__ hout, int* __restrict__ cnt,
                             __nv_bfloat16* __restrict__ ah, __nv_bfloat16* __restrict__ al)
{
    int row = blockIdx.x, c = threadIdx.x;
    __shared__ float red[CC];
    int4 s = slot[row];
    float v = x[row * CC + c];
    if (s.x >= 0)
        v += eoc[((size_t)s.x * NT + s.y) * CC + c]
           + eoc[((size_t)s.z * NT + s.w) * CC + c];
    x[row * CC + c] = v;
    if (row == 0 && c < NE) cnt[c] = 0;      // reset for next layer's router
    red[c] = v; __syncthreads();
    for (int st = 64; st > 0; st >>= 1) { if (c < st) red[c] += red[c + st]; __syncthreads(); }
    float mean = red[0] * (1.0f / CC);
    __syncthreads();
    float d = v - mean;
    red[c] = d * d; __syncthreads();
    for (int st = 64; st > 0; st >>= 1) { if (c < st) red[c] += red[c + st]; __syncthreads(); }
    float var = red[0] * (1.0f / CC);
    float hv = d / sqrtf(var + 1e-5f) * g[c] + b[c];
    hout[row * CC + c] = hv;
    if (ah) {                                // last layer: emit bf16 hi/lo split
        __nv_bfloat16 hi = __float2bfloat16(hv);
        ah[row * CC + c] = hi;
        al[row * CC + c] = __float2bfloat16(hv - __bfloat162float(hi));
    }
}

// -------------------- FFMA2 helper ----------------------------------------
__device__ __forceinline__ void ffma2(u64 &d, u64 a, u64 b)
{
    asm("fma.rn.f32x2 %0, %1, %2, %0;" : "+l"(d) : "l"(a), "l"(b));
}

enum { EPI_BIAS = 0, EPI_RELU = 1, EPI_RESID = 2, EPI_GATE_WR = 3 };

// -------------------- 128x128 SGEMM (QKV / MoE compact) --------------------
#define QM 128
#define QN 128
#define QK 16

template<int EPI, int INDA>
__global__ void __launch_bounds__(256, 2)
sgemm128_k(const float* __restrict__ A, const float* __restrict__ B,
           const float* __restrict__ bias, float* __restrict__ C,
           int M, int N, int K, const float* __restrict__ gates, int gstride,
           long zsA, long zsB, long zsBias, long zsC,
           const int* __restrict__ rows_all, const int* __restrict__ cnts)
{
    const int z  = blockIdx.z;
    const int Mz = cnts ? cnts[z] : M;
    const int m0 = blockIdx.y * QM;
    if (m0 >= Mz) return;

    __shared__ __align__(16) float  As [2][QK][QM];
    __shared__ __align__(16) float2 Bs2[2][QK][QN];
    const int tid = threadIdx.x;
    const int tx = tid & 15, ty = tid >> 4;
    const int n0 = blockIdx.x * QN;
    A += (size_t)z * zsA; B += (size_t)z * zsB; C += (size_t)z * zsC;
    const float* bz = bias ? bias + (size_t)z * zsBias : nullptr;
    const int* rows = rows_all ? rows_all + (size_t)z * NT : nullptr;

    const int am = tid >> 1, ak = (tid & 1) * 8;
    const int bk = tid >> 5, bn = (tid & 31) * 4;

    size_t arow;
    {
        int r = m0 + am;
        if (INDA) {
            int rr = (r < Mz) ? r : (Mz - 1);
            arow = (size_t)rows[rr];
        } else {
            arow = (size_t)r;
        }
    }
    const float* Abase = A + arow * (size_t)K;

    u64 acc[4][8];
#pragma unroll
    for (int i = 0; i < 4; i++)
#pragma unroll
        for (int j = 0; j < 8; j++) acc[i][j] = 0ull;

    float4 pa0, pa1;
    float  pb[2][4];
    {
        pa0 = *reinterpret_cast<const float4*>(Abase + ak);
        pa1 = *reinterpret_cast<const float4*>(Abase + ak + 4);
#pragma unroll
        for (int r = 0; r < 2; r++) {
            int kk = bk + r * 8;
#pragma unroll
            for (int j = 0; j < 4; j++) {
                int n = n0 + bn + j;
                pb[r][j] = (n < N) ? B[(size_t)kk * N + n] : 0.f;
            }
        }
    }

    const int ktiles = K >> 4;
    for (int kt = 0; kt < ktiles; kt++) {
        const int sb = kt & 1;
        As[sb][ak + 0][am] = pa0.x; As[sb][ak + 1][am] = pa0.y;
        As[sb][ak + 2][am] = pa0.z; As[sb][ak + 3][am] = pa0.w;
        As[sb][ak + 4][am] = pa1.x; As[sb][ak + 5][am] = pa1.y;
        As[sb][ak + 6][am] = pa1.z; As[sb][ak + 7][am] = pa1.w;
#pragma unroll
        for (int r = 0; r < 2; r++)
#pragma unroll
            for (int j = 0; j < 4; j++)
                Bs2[sb][bk + r * 8][bn + j] = make_float2(pb[r][j], pb[r][j]);
        __syncthreads();

        if (kt + 1 < ktiles) {
            int k0 = (kt + 1) * QK;
            pa0 = *reinterpret_cast<const float4*>(Abase + k0 + ak);
            pa1 = *reinterpret_cast<const float4*>(Abase + k0 + ak + 4);
#pragma unroll
            for (int r = 0; r < 2; r++) {
                int kk = k0 + bk + r * 8;
#pragma unroll
                for (int j = 0; j < 4; j++) {
                    int n = n0 + bn + j;
                    pb[r][j] = (n < N) ? B[(size_t)kk * N + n] : 0.f;
                }
            }
        }

#pragma unroll
        for (int k = 0; k < QK; k++) {
            u64 a[4];
#pragma unroll
            for (int i = 0; i < 4; i++)
                a[i] = *reinterpret_cast<const u64*>(&As[sb][k][ty * 8 + 2 * i]);
            u64 b[8];
#pragma unroll
            for (int j4 = 0; j4 < 4; j4++) {
                ulonglong2 v = *reinterpret_cast<const ulonglong2*>(&Bs2[sb][k][tx * 2 + 32 * j4]);
                b[2 * j4] = v.x; b[2 * j4 + 1] = v.y;
            }
#pragma unroll
            for (int i = 0; i < 4; i++)
#pragma unroll
                for (int j = 0; j < 8; j++)
                    ffma2(acc[i][j], a[i], b[j]);
        }
    }

    float bv[8];
#pragma unroll
    for (int j4 = 0; j4 < 4; j4++) {
        int n = n0 + tx * 2 + 32 * j4;
        bv[2 * j4]     = (bz && n     < N) ? bz[n]     : 0.f;
        bv[2 * j4 + 1] = (bz && n + 1 < N) ? bz[n + 1] : 0.f;
    }

#pragma unroll
    for (int mp = 0; mp < 4; mp++) {
#pragma unroll
        for (int hh = 0; hh < 2; hh++) {
            int m = m0 + ty * 8 + mp * 2 + hh;
            if (m >= Mz) continue;
            float gate = 1.f;
            if (EPI == EPI_GATE_WR) {
                int tok = rows ? rows[m] : m;
                gate = gates[(size_t)tok * gstride + z];
            }
            size_t rowb = (size_t)m * N;
#pragma unroll
            for (int j4 = 0; j4 < 4; j4++) {
                int n = n0 + tx * 2 + 32 * j4;
                u64 t0 = acc[mp][2 * j4], t1 = acc[mp][2 * j4 + 1];
                float v0 = hh ? __uint_as_float((unsigned)(t0 >> 32))
                              : __uint_as_float((unsigned)(t0 & 0xffffffffull));
                float v1 = hh ? __uint_as_float((unsigned)(t1 >> 32))
                              : __uint_as_float((unsigned)(t1 & 0xffffffffull));
                v0 += bv[2 * j4]; v1 += bv[2 * j4 + 1];
                if (EPI == EPI_RELU)    { v0 = fmaxf(v0, 0.f); v1 = fmaxf(v1, 0.f); }
                if (EPI == EPI_GATE_WR) { v0 *= gate; v1 *= gate; }
                size_t o = rowb + n;
                if (n + 1 < N && (o & 1) == 0) {
                    *reinterpret_cast<float2*>(&C[o]) = make_float2(v0, v1);
                } else {
                    if (n < N)     C[o]     = v0;
                    if (n + 1 < N) C[o + 1] = v1;
                }
            }
        }
    }
}

// -------------------- mma.sync bf16x3 LM head ------------------------------
// D[4096, VV] = Ah*Bh^T + Al*Bh^T + Ah*Bl^T, fp32 accum in registers.
// CTA: A tile 128m x K=128 resident in smem (hi+lo); LM_NTILES n-tiles of 64.
// Mainloop = R13 form (no long-lived prefetch registers). Next tile's B is
// prefetched with cp.async (zero register cost) after the post-mainloop sync,
// overlapping the epilogue's STG work; wait_group before the next mainloop.
__global__ void __launch_bounds__(256, 2)
lmhead_mma_k(const __nv_bfloat16* __restrict__ ah, const __nv_bfloat16* __restrict__ al,
             const __nv_bfloat16* __restrict__ bh, const __nv_bfloat16* __restrict__ bl,
             const float* __restrict__ bias, float* __restrict__ out)
{
    extern __shared__ __align__(16) __nv_bfloat16 sm[];
    __nv_bfloat16* sAh = sm;
    __nv_bfloat16* sAl = sm + 128 * LMS;
    __nv_bfloat16* sBh = sm + 2 * 128 * LMS;
    __nv_bfloat16* sBl = sBh + 64 * LMS;
    const int tid = threadIdx.x;
    const int m0 = blockIdx.x * 128;
    const int nbase = blockIdx.y * LM_NTILES * 64;

    const int brow = tid >> 4, bcol = (tid & 15) * 8;   // B staging coords
    const uint32_t sBh_u = smem_u32(sBh), sBl_u = smem_u32(sBl);

    // B(0) via cp.async (overlaps A's LDG+STS below), A direct
#pragma unroll
    for (int i = 0; i < 4; i++) {
        int row = brow + i * 16;
        cp_async16(sBh_u + (uint32_t)(row * LMS + bcol) * 2,
                   bh + (size_t)(nbase + row) * CC + bcol);
        cp_async16(sBl_u + (uint32_t)(row * LMS + bcol) * 2,
                   bl + (size_t)(nbase + row) * CC + bcol);
    }
    CP_COMMIT();
#pragma unroll
    for (int i = 0; i < 8; i++) {
        int idx = tid + i * 256; int row = idx >> 4, c = (idx & 15) * 8;
        *reinterpret_cast<uint4*>(sAh + row * LMS + c) =
            *reinterpret_cast<const uint4*>(ah + (size_t)(m0 + row) * CC + c);
        *reinterpret_cast<uint4*>(sAl + row * LMS + c) =
            *reinterpret_cast<const uint4*>(al + (size_t)(m0 + row) * CC + c);
    }
    CP_WAIT0();
    __syncthreads();

    const int w = tid >> 5, lane = tid & 31;
    const int wm = w >> 1, wn = w & 1;

    const __nv_bfloat16* Ap[3] = { sAh, sAl, sAh };
    const __nv_bfloat16* Bp[3] = { sBh, sBh, sBl };

    for (int nt = 0; nt < LM_NTILES; nt++) {
        const int n0 = nbase + nt * 64;

        float acc[2][4][4];
#pragma unroll
        for (int mt = 0; mt < 2; mt++)
#pragma unroll
            for (int ntl = 0; ntl < 4; ntl++)
#pragma unroll
                for (int q = 0; q < 4; q++) acc[mt][ntl][q] = 0.f;

#pragma unroll
        for (int pass = 0; pass < 3; pass++) {
            const uint32_t abase = smem_u32(Ap[pass]);
            const uint32_t bbase = smem_u32(Bp[pass]);
#pragma unroll
            for (int ks = 0; ks < 8; ks++) {
                const int k0 = ks * 16;
                uint32_t af[2][4];
#pragma unroll
                for (int mt = 0; mt < 2; mt++) {
                    int row = wm * 32 + mt * 16 + (lane & 15);
                    ldmatrix_x4(af[mt], abase + (uint32_t)(row * LMS + k0 + (lane >> 4) * 8) * 2);
                }
                uint32_t bf[4][2];
#pragma unroll
                for (int ntl = 0; ntl < 4; ntl++) {
                    int nr = wn * 32 + ntl * 8 + (lane & 7);
                    ldmatrix_x2(bf[ntl], bbase + (uint32_t)(nr * LMS + k0 + ((lane >> 3) & 1) * 8) * 2);
                }
#pragma unroll
                for (int mt = 0; mt < 2; mt++)
#pragma unroll
                    for (int ntl = 0; ntl < 4; ntl++)
                        mma16816(acc[mt][ntl], af[mt], bf[ntl]);
            }
        }

        __syncthreads();   // all warps done reading B(nt)

        // cp.async prefetch of B(nt+1): zero registers, overlaps epilogue STGs
        if (nt + 1 < LM_NTILES) {
#pragma unroll
            for (int i = 0; i < 4; i++) {
                int row = brow + i * 16;
                cp_async16(sBh_u + (uint32_t)(row * LMS + bcol) * 2,
                           bh + (size_t)(n0 + 64 + row) * CC + bcol);
                cp_async16(sBl_u + (uint32_t)(row * LMS + bcol) * 2,
                           bl + (size_t)(n0 + 64 + row) * CC + bcol);
            }
            CP_COMMIT();
        }

        // epilogue: D frag c0,c1 -> (m = lane>>2, n = (lane&3)*2+{0,1}); c2,c3 -> m+8
#pragma unroll
        for (int ntl = 0; ntl < 4; ntl++) {
            int n = n0 + wn * 32 + ntl * 8 + (lane & 3) * 2;
            float b0 = (n     < VV) ? bias[n]     : 0.f;
            float b1 = (n + 1 < VV) ? bias[n + 1] : 0.f;
#pragma unroll
            for (int mt = 0; mt < 2; mt++) {
#pragma unroll
                for (int half = 0; half < 2; half++) {
                    int m = m0 + wm * 32 + mt * 16 + (lane >> 2) + half * 8;
                    float v0 = acc[mt][ntl][half * 2 + 0] + b0;
                    float v1 = acc[mt][ntl][half * 2 + 1] + b1;
                    size_t o = (size_t)m * VV + n;
                    if (n + 1 < VV && (o & 1) == 0) {
                        *reinterpret_cast<float2*>(out + o) = make_float2(v0, v1);
                    } else {
                        if (n     < VV) out[o]     = v0;
                        if (n + 1 < VV) out[o + 1] = v1;
                    }
                }
            }
        }
        if (nt + 1 < LM_NTILES) CP_WAIT0();
        __syncthreads();   // B(nt+1) visible before next mainloop
    }
}

// -------------------- host orchestration ----------------------------------
extern "C" void kernel_launch(void* const* d_in, const int* in_sizes, int n_in,
                              void* d_out, int out_size)
{
    (void)in_sizes; (void)n_in; (void)out_size;
    const int*   idx  = (const int*)  d_in[0];
    const float* tok  = (const float*)d_in[1];
    const float* pos  = (const float*)d_in[2];
    const float* ln1g = (const float*)d_in[3];
    const float* ln1b = (const float*)d_in[4];
    const float* Wq   = (const float*)d_in[5];
    const float* Wk   = (const float*)d_in[6];
    const float* Wv   = (const float*)d_in[7];
    const float* Wo   = (const float*)d_in[8];
    const float* bo   = (const float*)d_in[9];
    const float* ln2g = (const float*)d_in[10];
    const float* ln2b = (const float*)d_in[11];
    const float* Wr   = (const float*)d_in[12];
    const float* br   = (const float*)d_in[13];
    const float* Wn   = (const float*)d_in[14];
    const float* bn   = (const float*)d_in[15];
    const float* Wsr  = (const float*)d_in[16];
    const float* bsr  = (const float*)d_in[17];
    const float* W1   = (const float*)d_in[18];
    const float* b1   = (const float*)d_in[19];
    const float* W2   = (const float*)d_in[20];
    const float* b2   = (const float*)d_in[21];
    const float* lnfg = (const float*)d_in[22];
    const float* lnfb = (const float*)d_in[23];
    const float* Wlm  = (const float*)d_in[24];
    const float* blm  = (const float*)d_in[25];
    float* out = (float*)d_out;

    float *x, *h, *qkv, *nx, *h1c, *eoc, *gates, *wp;
    int *cnt, *list; int4* slot;
    __nv_bfloat16 *bhp, *blp, *ahp, *alp;
    cudaGetSymbolAddress((void**)&x,     g_x);
    cudaGetSymbolAddress((void**)&h,     g_h);
    cudaGetSymbolAddress((void**)&qkv,   g_qkv);
    cudaGetSymbolAddress((void**)&nx,    g_nx);
    cudaGetSymbolAddress((void**)&h1c,   g_h1c);
    cudaGetSymbolAddress((void**)&eoc,   g_eoc);
    cudaGetSymbolAddress((void**)&gates, g_gates);
    cudaGetSymbolAddress((void**)&cnt,   g_cnt);
    cudaGetSymbolAddress((void**)&list,  g_list);
    cudaGetSymbolAddress((void**)&slot,  g_slot);
    cudaGetSymbolAddress((void**)&wp,    g_wpack);
    cudaGetSymbolAddress((void**)&bhp,   g_bh);
    cudaGetSymbolAddress((void**)&blp,   g_bl);
    cudaGetSymbolAddress((void**)&ahp,   g_ah);
    cudaGetSymbolAddress((void**)&alp,   g_al);

    embed_k<<<NT * CC / 256, 256>>>(idx, tok, pos, x, cnt);
    pack_qkv_all_k<<<NL * CC * 384 / 256, 256>>>(Wq, Wk, Wv, wp);
    pack_b_k<<<dim3(LM_NPAD / 32, CC / 32), dim3(32, 32)>>>(Wlm, bhp, blp);
    layernorm_k<<<NT, CC>>>(x, ln1g, ln1b, h);

    cudaFuncSetAttribute(attn_proj_k, cudaFuncAttributeMaxDynamicSharedMemorySize, AP_SMEM);

    for (int l = 0; l < NL; l++) {
        sgemm128_k<EPI_BIAS, 0><<<dim3(384 / QN, NT / QM), 256>>>(
            h, wp + (size_t)l * CC * 384, nullptr, qkv, NT, 384, CC, nullptr, 0,
            0, 0, 0, 0, nullptr, nullptr);
        attn_proj_k<<<NT / TT, 1024, AP_SMEM>>>(qkv, Wo + l * CC * CC, bo + l * CC, x);
        router_ln_k<<<NT, CC>>>(x, ln2g + l * CC, ln2b + l * CC,
                                Wr + l * CC * NE, br + l * NE,
                                Wn + l * CC * NE, bn + l * NE,
                                Wsr + l * CC, bsr + l,
                                nx, gates, cnt, list, slot, l);
        sgemm128_k<EPI_RELU, 1><<<dim3(FF / QN, NT / QM, NE), 256>>>(
            nx, W1 + (size_t)l * NE * CC * FF, b1 + (size_t)l * NE * FF, h1c,
            NT, FF, CC, nullptr, 0,
            0, (long)CC * FF, FF, (long)NT * FF, list, cnt);
        sgemm128_k<EPI_GATE_WR, 0><<<dim3(CC / QN, NT / QM, NE), 256>>>(
            h1c, W2 + (size_t)l * NE * FF * CC, b2 + (size_t)l * NE * CC, eoc,
            NT, CC, FF, gates, NE,
            (long)NT * FF, (long)FF * CC, CC, (long)NT * CC, list, cnt);
        const float* gnext = (l + 1 < NL) ? (ln1g + (l + 1) * CC) : lnfg;
        const float* bnext = (l + 1 < NL) ? (ln1b + (l + 1) * CC) : lnfb;
        const bool last = (l + 1 == NL);
        combine_ln_k<<<NT, CC>>>(x, eoc, slot, gnext, bnext, h, cnt,
                                 last ? ahp : nullptr, last ? alp : nullptr);
    }

    cudaFuncSetAttribute(lmhead_mma_k, cudaFuncAttributeMaxDynamicSharedMemorySize, LM_SMEM);
    lmhead_mma_k<<<dim3(NT / 128, LM_NPAD / (64 * LM_NTILES)), 256, LM_SMEM>>>(
        ahp, alp, bhp, blp, blm, out);
}